// round 1
// baseline (speedup 1.0000x reference)
#include <cuda_runtime.h>

#define NROI 4000
#define CCH  64
#define FH   240
#define FW   240
#define NPIX (FH*FW)

// ---------------- scratch (no allocations allowed) ----------------
__device__ float g_fmT[NPIX * CCH];        // HWC transposed feature map (14.7 MB)
__device__ float g_pooled[3 * NROI * CCH]; // pooled features per scale
__device__ float g_h[3 * NROI * CCH];      // head outputs per scale
__device__ float g_gmean[CCH];             // global mean per channel
__device__ float g_bp1eff[128];            // bp1 + head(g) @ P1[192:256]

// ---------------- 1) transpose CHW -> HWC ----------------
__global__ void transpose_kernel(const float* __restrict__ fm) {
    __shared__ float tile[64][65];
    int pix0 = blockIdx.x * 64;
    int tid  = threadIdx.x;
    int lane = tid & 63;     // pixel offset on load, channel on store
    int grp  = tid >> 6;     // 0..3
    #pragma unroll
    for (int c = grp; c < 64; c += 4)
        tile[c][lane] = fm[c * NPIX + pix0 + lane];
    __syncthreads();
    #pragma unroll
    for (int p = grp; p < 64; p += 4)
        g_fmT[(pix0 + p) * 64 + lane] = tile[lane][p];
}

// ---------------- 2) global channel mean ----------------
__global__ void gmean_kernel(const float* __restrict__ fm) {
    int ch = blockIdx.x, tid = threadIdx.x;
    const float* p = fm + ch * NPIX;
    float s = 0.f;
    for (int i = tid; i < NPIX; i += 256) s += p[i];
    __shared__ float sm[256];
    sm[tid] = s;
    __syncthreads();
    for (int off = 128; off; off >>= 1) {
        if (tid < off) sm[tid] += sm[tid + off];
        __syncthreads();
    }
    if (tid == 0) g_gmean[ch] = sm[0] * (1.0f / (float)NPIX);
}

// ---------------- 3) head(g) folded into bp1 ----------------
__global__ void head_const_kernel(const float* __restrict__ W1, const float* __restrict__ b1,
                                  const float* __restrict__ W2, const float* __restrict__ b2,
                                  const float* __restrict__ P1, const float* __restrict__ bp1) {
    __shared__ float gs[64];
    __shared__ float t[128];
    __shared__ float hg[64];
    int tid = threadIdx.x;  // 128 threads
    if (tid < 64) gs[tid] = g_gmean[tid];
    __syncthreads();
    float a = b1[tid];
    #pragma unroll 8
    for (int c = 0; c < 64; c++) a = fmaf(gs[c], W1[c * 128 + tid], a);
    t[tid] = fmaxf(a, 0.f);
    __syncthreads();
    if (tid < 64) {
        float a2 = b2[tid];
        #pragma unroll 8
        for (int k = 0; k < 128; k++) a2 = fmaf(t[k], W2[k * 64 + tid], a2);
        hg[tid] = fmaxf(a2, 0.f);
    }
    __syncthreads();
    float be = bp1[tid];
    #pragma unroll 8
    for (int c = 0; c < 64; c++) be = fmaf(hg[c], P1[(192 + c) * 128 + tid], be);
    g_bp1eff[tid] = be;
}

// ---------------- 4) bilinear ROI average pooling ----------------
__global__ void pool_kernel(const float* __restrict__ boxes) {
    const int S_tab[3] = {3, 7, 11};
    int scale = blockIdx.y;
    int S = S_tab[scale];
    int n = blockIdx.x;
    int tid = threadIdx.x;
    int c = tid & 63;       // channel
    int slice = tid >> 6;   // 0..3 sample slices

    float bx1 = boxes[n * 4 + 0] * (2.0f / 960.0f) - 1.0f;
    float by1 = boxes[n * 4 + 1] * (2.0f / 960.0f) - 1.0f;
    float bx2 = boxes[n * 4 + 2] * (2.0f / 960.0f) - 1.0f;
    float by2 = boxes[n * 4 + 3] * (2.0f / 960.0f) - 1.0f;
    float cx = (bx1 + bx2) * 0.5f;
    float cy = (by1 + by2) * 0.5f;
    float w  = fmaxf(bx2 - bx1, 1e-6f);
    float h  = fmaxf(by2 - by1, 1e-6f);

    float acc = 0.f;
    int SS = S * S;
    for (int samp = slice; samp < SS; samp += 4) {
        int i = samp / S, j = samp - i * S;
        float basej = (2.0f * (float)j + 1.0f) / (float)S - 1.0f;
        float basei = (2.0f * (float)i + 1.0f) / (float)S - 1.0f;
        float gx = w * 0.5f * basej + cx;
        float gy = h * 0.5f * basei + cy;
        float ix = ((gx + 1.0f) * (float)FW - 1.0f) * 0.5f;
        float iy = ((gy + 1.0f) * (float)FH - 1.0f) * 0.5f;
        float x0f = floorf(ix), y0f = floorf(iy);
        float dx = ix - x0f, dy = iy - y0f;
        int x0 = (int)x0f, y0 = (int)y0f;
        int x1 = x0 + 1,   y1 = y0 + 1;
        bool vx0 = (x0 >= 0) && (x0 < FW);
        bool vx1 = (x1 >= 0) && (x1 < FW);
        bool vy0 = (y0 >= 0) && (y0 < FH);
        bool vy1 = (y1 >= 0) && (y1 < FH);
        float v00 = (vx0 && vy0) ? g_fmT[(y0 * FW + x0) * 64 + c] : 0.f;
        float v01 = (vx1 && vy0) ? g_fmT[(y0 * FW + x1) * 64 + c] : 0.f;
        float v10 = (vx0 && vy1) ? g_fmT[(y1 * FW + x0) * 64 + c] : 0.f;
        float v11 = (vx1 && vy1) ? g_fmT[(y1 * FW + x1) * 64 + c] : 0.f;
        acc += (v00 * (1.0f - dx) + v01 * dx) * (1.0f - dy)
             + (v10 * (1.0f - dx) + v11 * dx) * dy;
    }
    __shared__ float red[4][64];
    red[slice][c] = acc;
    __syncthreads();
    if (slice == 0) {
        float sum = red[0][c] + red[1][c] + red[2][c] + red[3][c];
        g_pooled[((size_t)scale * NROI + n) * 64 + c] = sum / (float)SS;
    }
}

// ---------------- 5) per-scale MLP head: relu(relu(X@W1+b1)@W2+b2) ----------------
// 64-row tile per block, 256 threads, dynamic smem.
__global__ void head_kernel(const float* __restrict__ W1, const float* __restrict__ b1,
                            const float* __restrict__ W2, const float* __restrict__ b2) {
    extern __shared__ float sh[];
    float* As  = sh;                 // 64*64
    float* W1s = As + 4096;          // 64*128
    float* W2s = W1s + 8192;         // 128*64
    float* Ts  = W2s + 8192;         // 64*128
    float* b1s = Ts + 8192;          // 128
    float* b2s = b1s + 128;          // 64

    int tid = threadIdx.x;
    int scale = blockIdx.y;
    int row0 = blockIdx.x * 64;
    const float* X    = g_pooled + (size_t)scale * NROI * CCH;
    float*       Hout = g_h      + (size_t)scale * NROI * CCH;

    // cooperative loads
    {
        const float4* X4 = (const float4*)(X + (size_t)row0 * 64);
        float4* As4 = (float4*)As;
        #pragma unroll
        for (int idx = tid; idx < 1024; idx += 256) {
            int r = idx >> 4;
            As4[idx] = (row0 + r < NROI) ? X4[idx] : make_float4(0.f, 0.f, 0.f, 0.f);
        }
        const float4* W14 = (const float4*)W1;
        float4* W1s4 = (float4*)W1s;
        #pragma unroll
        for (int idx = tid; idx < 2048; idx += 256) W1s4[idx] = W14[idx];
        const float4* W24 = (const float4*)W2;
        float4* W2s4 = (float4*)W2s;
        #pragma unroll
        for (int idx = tid; idx < 2048; idx += 256) W2s4[idx] = W24[idx];
        if (tid < 128) b1s[tid] = b1[tid];
        if (tid < 64)  b2s[tid] = b2[tid];
    }
    __syncthreads();

    int rg = tid >> 4;   // row group: rows rg*4..rg*4+3
    int cg = tid & 15;   // col group: phase A cols cg*8..+7

    // phase A: T = relu(A@W1 + b1), 64x128
    float acc[4][8];
    #pragma unroll
    for (int i = 0; i < 4; i++)
        #pragma unroll
        for (int j = 0; j < 8; j++) acc[i][j] = 0.f;

    #pragma unroll 4
    for (int k = 0; k < 64; k++) {
        float a[4];
        #pragma unroll
        for (int i = 0; i < 4; i++) a[i] = As[(rg * 4 + i) * 64 + k];
        float4 w0 = *(const float4*)&W1s[k * 128 + cg * 8];
        float4 w1 = *(const float4*)&W1s[k * 128 + cg * 8 + 4];
        float wv[8] = {w0.x, w0.y, w0.z, w0.w, w1.x, w1.y, w1.z, w1.w};
        #pragma unroll
        for (int i = 0; i < 4; i++)
            #pragma unroll
            for (int j = 0; j < 8; j++)
                acc[i][j] = fmaf(a[i], wv[j], acc[i][j]);
    }
    #pragma unroll
    for (int i = 0; i < 4; i++) {
        int r = rg * 4 + i;
        #pragma unroll
        for (int j = 0; j < 8; j++)
            Ts[r * 128 + cg * 8 + j] = fmaxf(acc[i][j] + b1s[cg * 8 + j], 0.f);
    }
    __syncthreads();

    // phase B: H = relu(T@W2 + b2), 64x64
    int cg2 = tid & 15;  // cols cg2*4..+3
    float acc2[4][4];
    #pragma unroll
    for (int i = 0; i < 4; i++)
        #pragma unroll
        for (int j = 0; j < 4; j++) acc2[i][j] = 0.f;

    #pragma unroll 4
    for (int k = 0; k < 128; k++) {
        float a[4];
        #pragma unroll
        for (int i = 0; i < 4; i++) a[i] = Ts[(rg * 4 + i) * 128 + k];
        float4 w = *(const float4*)&W2s[k * 64 + cg2 * 4];
        float wv[4] = {w.x, w.y, w.z, w.w};
        #pragma unroll
        for (int i = 0; i < 4; i++)
            #pragma unroll
            for (int j = 0; j < 4; j++)
                acc2[i][j] = fmaf(a[i], wv[j], acc2[i][j]);
    }
    #pragma unroll
    for (int i = 0; i < 4; i++) {
        int r = row0 + rg * 4 + i;
        if (r < NROI) {
            float4 o;
            o.x = fmaxf(acc2[i][0] + b2s[cg2 * 4 + 0], 0.f);
            o.y = fmaxf(acc2[i][1] + b2s[cg2 * 4 + 1], 0.f);
            o.z = fmaxf(acc2[i][2] + b2s[cg2 * 4 + 2], 0.f);
            o.w = fmaxf(acc2[i][3] + b2s[cg2 * 4 + 3], 0.f);
            *(float4*)&Hout[(size_t)r * 64 + cg2 * 4] = o;
        }
    }
}

// ---------------- 6) final: out = relu(relu(cat@P1 + bp1eff)@P2 + bp2) ----------------
// cat = [h3 | h7 | h11] (global head folded into bp1eff). K tiled in 3 chunks of 64.
__global__ void final_kernel(const float* __restrict__ P1, const float* __restrict__ P2,
                             const float* __restrict__ bp2, float* __restrict__ out) {
    extern __shared__ float sh[];
    float* As  = sh;                 // 64*64 (reloaded per chunk)
    float* P1s = As + 4096;          // 64*128 (per chunk)
    float* P2s = P1s + 8192;         // 128*64
    float* Ts  = P2s + 8192;         // 64*128
    float* be  = Ts + 8192;          // 128
    float* b2s = be + 128;           // 64

    int tid = threadIdx.x;
    int row0 = blockIdx.x * 64;

    {
        const float4* P24 = (const float4*)P2;
        float4* P2s4 = (float4*)P2s;
        #pragma unroll
        for (int idx = tid; idx < 2048; idx += 256) P2s4[idx] = P24[idx];
        if (tid < 128) be[tid] = g_bp1eff[tid];
        if (tid < 64)  b2s[tid] = bp2[tid];
    }

    int rg = tid >> 4;
    int cg = tid & 15;

    float acc[4][8];
    #pragma unroll
    for (int i = 0; i < 4; i++)
        #pragma unroll
        for (int j = 0; j < 8; j++) acc[i][j] = 0.f;

    for (int kb = 0; kb < 3; kb++) {
        __syncthreads();  // previous chunk compute done before reload
        const float4* X4 = (const float4*)(g_h + (size_t)kb * NROI * CCH + (size_t)row0 * 64);
        float4* As4 = (float4*)As;
        #pragma unroll
        for (int idx = tid; idx < 1024; idx += 256) {
            int r = idx >> 4;
            As4[idx] = (row0 + r < NROI) ? X4[idx] : make_float4(0.f, 0.f, 0.f, 0.f);
        }
        const float4* P14 = (const float4*)(P1 + (size_t)kb * 64 * 128);
        float4* P1s4 = (float4*)P1s;
        #pragma unroll
        for (int idx = tid; idx < 2048; idx += 256) P1s4[idx] = P14[idx];
        __syncthreads();

        #pragma unroll 4
        for (int k = 0; k < 64; k++) {
            float a[4];
            #pragma unroll
            for (int i = 0; i < 4; i++) a[i] = As[(rg * 4 + i) * 64 + k];
            float4 w0 = *(const float4*)&P1s[k * 128 + cg * 8];
            float4 w1 = *(const float4*)&P1s[k * 128 + cg * 8 + 4];
            float wv[8] = {w0.x, w0.y, w0.z, w0.w, w1.x, w1.y, w1.z, w1.w};
            #pragma unroll
            for (int i = 0; i < 4; i++)
                #pragma unroll
                for (int j = 0; j < 8; j++)
                    acc[i][j] = fmaf(a[i], wv[j], acc[i][j]);
        }
    }

    #pragma unroll
    for (int i = 0; i < 4; i++) {
        int r = rg * 4 + i;
        #pragma unroll
        for (int j = 0; j < 8; j++)
            Ts[r * 128 + cg * 8 + j] = fmaxf(acc[i][j] + be[cg * 8 + j], 0.f);
    }
    __syncthreads();

    int cg2 = tid & 15;
    float acc2[4][4];
    #pragma unroll
    for (int i = 0; i < 4; i++)
        #pragma unroll
        for (int j = 0; j < 4; j++) acc2[i][j] = 0.f;

    #pragma unroll 4
    for (int k = 0; k < 128; k++) {
        float a[4];
        #pragma unroll
        for (int i = 0; i < 4; i++) a[i] = Ts[(rg * 4 + i) * 128 + k];
        float4 w = *(const float4*)&P2s[k * 64 + cg2 * 4];
        float wv[4] = {w.x, w.y, w.z, w.w};
        #pragma unroll
        for (int i = 0; i < 4; i++)
            #pragma unroll
            for (int j = 0; j < 4; j++)
                acc2[i][j] = fmaf(a[i], wv[j], acc2[i][j]);
    }
    #pragma unroll
    for (int i = 0; i < 4; i++) {
        int r = row0 + rg * 4 + i;
        if (r < NROI) {
            float4 o;
            o.x = fmaxf(acc2[i][0] + b2s[cg2 * 4 + 0], 0.f);
            o.y = fmaxf(acc2[i][1] + b2s[cg2 * 4 + 1], 0.f);
            o.z = fmaxf(acc2[i][2] + b2s[cg2 * 4 + 2], 0.f);
            o.w = fmaxf(acc2[i][3] + b2s[cg2 * 4 + 3], 0.f);
            *(float4*)&out[(size_t)r * 64 + cg2 * 4] = o;
        }
    }
}

// ---------------- launch ----------------
extern "C" void kernel_launch(void* const* d_in, const int* in_sizes, int n_in,
                              void* d_out, int out_size) {
    const float* fm    = (const float*)d_in[0];
    const float* boxes = (const float*)d_in[1];
    const float* W1    = (const float*)d_in[2];
    const float* b1    = (const float*)d_in[3];
    const float* W2    = (const float*)d_in[4];
    const float* b2    = (const float*)d_in[5];
    const float* P1    = (const float*)d_in[6];
    const float* bp1   = (const float*)d_in[7];
    const float* P2    = (const float*)d_in[8];
    const float* bp2   = (const float*)d_in[9];
    float* out = (float*)d_out;

    const int SMEM = (4096 + 8192 + 8192 + 8192 + 128 + 64) * 4;  // 115456 B
    cudaFuncSetAttribute(head_kernel,  cudaFuncAttributeMaxDynamicSharedMemorySize, SMEM);
    cudaFuncSetAttribute(final_kernel, cudaFuncAttributeMaxDynamicSharedMemorySize, SMEM);

    transpose_kernel<<<NPIX / 64, 256>>>(fm);
    gmean_kernel<<<64, 256>>>(fm);
    head_const_kernel<<<1, 128>>>(W1, b1, W2, b2, P1, bp1);

    dim3 pgrid(NROI, 3);
    pool_kernel<<<pgrid, 256>>>(boxes);

    const int NT = (NROI + 63) / 64;  // 63 row tiles
    dim3 hgrid(NT, 3);
    head_kernel<<<hgrid, 256, SMEM>>>(W1, b1, W2, b2);
    final_kernel<<<NT, 256, SMEM>>>(P1, P2, bp2, out);
}

// round 2
// speedup vs baseline: 1.5947x; 1.5947x over previous
#include <cuda_runtime.h>
#include <cuda_fp16.h>

#define NROI 4000
#define CCH  64
#define FH   240
#define FW   240
#define NPIX (FH*FW)

// ---------------- scratch (no allocations allowed) ----------------
__device__ __half2 g_fmTh[NPIX * 32];      // HWC fp16 feature map (7.4 MB), 32 half2 = 64ch
__device__ float g_pooled[3 * NROI * CCH]; // pooled features per scale
__device__ float g_h[3 * NROI * CCH];      // head outputs per scale
__device__ float g_gmean[CCH];             // global mean per channel
__device__ float g_bp1eff[128];            // bp1 + head(g) @ P1[192:256]

// ---------------- 1) transpose CHW fp32 -> HWC fp16 (half2 packed) ----------------
__global__ void transpose_kernel(const float* __restrict__ fm) {
    __shared__ float tile[64][65];
    int pix0 = blockIdx.x * 64;
    int tid  = threadIdx.x;
    int lane = tid & 63;     // pixel offset on load
    int grp  = tid >> 6;     // 0..3
    #pragma unroll
    for (int c = grp; c < 64; c += 4)
        tile[c][lane] = fm[c * NPIX + pix0 + lane];
    __syncthreads();
    int c2 = tid & 31;       // channel pair
    int pg = tid >> 5;       // 0..7
    #pragma unroll
    for (int p = pg; p < 64; p += 8)
        g_fmTh[(pix0 + p) * 32 + c2] =
            __floats2half2_rn(tile[2 * c2][p], tile[2 * c2 + 1][p]);
}

// ---------------- 2) global channel mean (fp32 source) ----------------
__global__ void gmean_kernel(const float* __restrict__ fm) {
    int ch = blockIdx.x, tid = threadIdx.x;
    const float* p = fm + ch * NPIX;
    float s = 0.f;
    for (int i = tid; i < NPIX; i += 256) s += p[i];
    __shared__ float sm[256];
    sm[tid] = s;
    __syncthreads();
    for (int off = 128; off; off >>= 1) {
        if (tid < off) sm[tid] += sm[tid + off];
        __syncthreads();
    }
    if (tid == 0) g_gmean[ch] = sm[0] * (1.0f / (float)NPIX);
}

// ---------------- 3) head(g) folded into bp1 ----------------
__global__ void head_const_kernel(const float* __restrict__ W1, const float* __restrict__ b1,
                                  const float* __restrict__ W2, const float* __restrict__ b2,
                                  const float* __restrict__ P1, const float* __restrict__ bp1) {
    __shared__ float gs[64];
    __shared__ float t[128];
    __shared__ float hg[64];
    int tid = threadIdx.x;  // 128 threads
    if (tid < 64) gs[tid] = g_gmean[tid];
    __syncthreads();
    float a = b1[tid];
    #pragma unroll 8
    for (int c = 0; c < 64; c++) a = fmaf(gs[c], W1[c * 128 + tid], a);
    t[tid] = fmaxf(a, 0.f);
    __syncthreads();
    if (tid < 64) {
        float a2 = b2[tid];
        #pragma unroll 8
        for (int k = 0; k < 128; k++) a2 = fmaf(t[k], W2[k * 64 + tid], a2);
        hg[tid] = fmaxf(a2, 0.f);
    }
    __syncthreads();
    float be = bp1[tid];
    #pragma unroll 8
    for (int c = 0; c < 64; c++) be = fmaf(hg[c], P1[(192 + c) * 128 + tid], be);
    g_bp1eff[tid] = be;
}

// ---------------- 4) bilinear ROI average pooling (fp16 fm, templated S) ----------------
template<int S>
__global__ void pool_kernel(const float* __restrict__ boxes, int scale) {
    constexpr int SS = S * S;
    int n    = blockIdx.x;
    int tid  = threadIdx.x;
    int lane = tid & 31;   // channel pair 2*lane, 2*lane+1
    int warp = tid >> 5;   // sample slice 0..7

    float bx1 = boxes[n * 4 + 0];
    float by1 = boxes[n * 4 + 1];
    float bx2 = boxes[n * 4 + 2];
    float by2 = boxes[n * 4 + 3];
    // normalized coords
    float nx1 = bx1 * (2.0f / 960.0f) - 1.0f;
    float ny1 = by1 * (2.0f / 960.0f) - 1.0f;
    float nx2 = bx2 * (2.0f / 960.0f) - 1.0f;
    float ny2 = by2 * (2.0f / 960.0f) - 1.0f;
    float cx = (nx1 + nx2) * 0.5f;
    float cy = (ny1 + ny2) * 0.5f;
    float w  = fmaxf(nx2 - nx1, 1e-6f);
    float h  = fmaxf(ny2 - ny1, 1e-6f);
    // ix(j) = j*stepx + ixb ; iy(i) = i*stepy + iyb  (image-space sample coords)
    float stepx = w * (120.0f / (float)S);
    float stepy = h * (120.0f / (float)S);
    float ixb = fmaf(w * 60.0f, (1.0f / (float)S - 1.0f), fmaf(cx, 120.0f, 119.5f));
    float iyb = fmaf(h * 60.0f, (1.0f / (float)S - 1.0f), fmaf(cy, 120.0f, 119.5f));

    float accx = 0.f, accy = 0.f;
    for (int samp = warp; samp < SS; samp += 8) {
        int i = samp / S;
        int j = samp - i * S;
        float ix = fmaf((float)j, stepx, ixb);
        float iy = fmaf((float)i, stepy, iyb);
        float x0f = floorf(ix), y0f = floorf(iy);
        float dx = ix - x0f, dy = iy - y0f;
        int x0 = (int)x0f, y0 = (int)y0f;
        int x1 = x0 + 1,   y1 = y0 + 1;
        float wx0 = ((unsigned)x0 < FW) ? (1.f - dx) : 0.f;
        float wx1 = ((unsigned)x1 < FW) ? dx : 0.f;
        float wy0 = ((unsigned)y0 < FH) ? (1.f - dy) : 0.f;
        float wy1 = ((unsigned)y1 < FH) ? dy : 0.f;
        int xc0 = max(0, min(x0, FW - 1));
        int xc1 = max(0, min(x1, FW - 1));
        int yc0 = max(0, min(y0, FH - 1));
        int yc1 = max(0, min(y1, FH - 1));
        const __half2* r0 = g_fmTh + (yc0 * FW) * 32 + lane;
        const __half2* r1 = g_fmTh + (yc1 * FW) * 32 + lane;
        float2 f00 = __half22float2(r0[xc0 * 32]);
        float2 f01 = __half22float2(r0[xc1 * 32]);
        float2 f10 = __half22float2(r1[xc0 * 32]);
        float2 f11 = __half22float2(r1[xc1 * 32]);
        float tx = fmaf(f00.x, wx0, f01.x * wx1);
        float ty = fmaf(f00.y, wx0, f01.y * wx1);
        float bx = fmaf(f10.x, wx0, f11.x * wx1);
        float by = fmaf(f10.y, wx0, f11.y * wx1);
        accx = fmaf(wy0, tx, fmaf(wy1, bx, accx));
        accy = fmaf(wy0, ty, fmaf(wy1, by, accy));
    }

    __shared__ float2 red[8][32];
    red[warp][lane] = make_float2(accx, accy);
    __syncthreads();
    if (warp == 0) {
        float2 s = red[0][lane];
        #pragma unroll
        for (int wq = 1; wq < 8; wq++) {
            s.x += red[wq][lane].x;
            s.y += red[wq][lane].y;
        }
        float2* outp = (float2*)&g_pooled[((size_t)scale * NROI + n) * 64 + 2 * lane];
        *outp = make_float2(s.x * (1.0f / (float)SS), s.y * (1.0f / (float)SS));
    }
}

// ---------------- 5) per-scale MLP head: relu(relu(X@W1+b1)@W2+b2) ----------------
__global__ void head_kernel(const float* __restrict__ W1, const float* __restrict__ b1,
                            const float* __restrict__ W2, const float* __restrict__ b2) {
    extern __shared__ float sh[];
    float* As  = sh;                 // 64*64
    float* W1s = As + 4096;          // 64*128
    float* W2s = W1s + 8192;         // 128*64
    float* Ts  = W2s + 8192;         // 64*128
    float* b1s = Ts + 8192;          // 128
    float* b2s = b1s + 128;          // 64

    int tid = threadIdx.x;
    int scale = blockIdx.y;
    int row0 = blockIdx.x * 64;
    const float* X    = g_pooled + (size_t)scale * NROI * CCH;
    float*       Hout = g_h      + (size_t)scale * NROI * CCH;

    {
        const float4* X4 = (const float4*)(X + (size_t)row0 * 64);
        float4* As4 = (float4*)As;
        #pragma unroll
        for (int idx = tid; idx < 1024; idx += 256) {
            int r = idx >> 4;
            As4[idx] = (row0 + r < NROI) ? X4[idx] : make_float4(0.f, 0.f, 0.f, 0.f);
        }
        const float4* W14 = (const float4*)W1;
        float4* W1s4 = (float4*)W1s;
        #pragma unroll
        for (int idx = tid; idx < 2048; idx += 256) W1s4[idx] = W14[idx];
        const float4* W24 = (const float4*)W2;
        float4* W2s4 = (float4*)W2s;
        #pragma unroll
        for (int idx = tid; idx < 2048; idx += 256) W2s4[idx] = W24[idx];
        if (tid < 128) b1s[tid] = b1[tid];
        if (tid < 64)  b2s[tid] = b2[tid];
    }
    __syncthreads();

    int rg = tid >> 4;
    int cg = tid & 15;

    float acc[4][8];
    #pragma unroll
    for (int i = 0; i < 4; i++)
        #pragma unroll
        for (int j = 0; j < 8; j++) acc[i][j] = 0.f;

    #pragma unroll 4
    for (int k = 0; k < 64; k++) {
        float a[4];
        #pragma unroll
        for (int i = 0; i < 4; i++) a[i] = As[(rg * 4 + i) * 64 + k];
        float4 w0 = *(const float4*)&W1s[k * 128 + cg * 8];
        float4 w1 = *(const float4*)&W1s[k * 128 + cg * 8 + 4];
        float wv[8] = {w0.x, w0.y, w0.z, w0.w, w1.x, w1.y, w1.z, w1.w};
        #pragma unroll
        for (int i = 0; i < 4; i++)
            #pragma unroll
            for (int j = 0; j < 8; j++)
                acc[i][j] = fmaf(a[i], wv[j], acc[i][j]);
    }
    #pragma unroll
    for (int i = 0; i < 4; i++) {
        int r = rg * 4 + i;
        #pragma unroll
        for (int j = 0; j < 8; j++)
            Ts[r * 128 + cg * 8 + j] = fmaxf(acc[i][j] + b1s[cg * 8 + j], 0.f);
    }
    __syncthreads();

    int cg2 = tid & 15;
    float acc2[4][4];
    #pragma unroll
    for (int i = 0; i < 4; i++)
        #pragma unroll
        for (int j = 0; j < 4; j++) acc2[i][j] = 0.f;

    #pragma unroll 4
    for (int k = 0; k < 128; k++) {
        float a[4];
        #pragma unroll
        for (int i = 0; i < 4; i++) a[i] = Ts[(rg * 4 + i) * 128 + k];
        float4 w = *(const float4*)&W2s[k * 64 + cg2 * 4];
        float wv[4] = {w.x, w.y, w.z, w.w};
        #pragma unroll
        for (int i = 0; i < 4; i++)
            #pragma unroll
            for (int j = 0; j < 4; j++)
                acc2[i][j] = fmaf(a[i], wv[j], acc2[i][j]);
    }
    #pragma unroll
    for (int i = 0; i < 4; i++) {
        int r = row0 + rg * 4 + i;
        if (r < NROI) {
            float4 o;
            o.x = fmaxf(acc2[i][0] + b2s[cg2 * 4 + 0], 0.f);
            o.y = fmaxf(acc2[i][1] + b2s[cg2 * 4 + 1], 0.f);
            o.z = fmaxf(acc2[i][2] + b2s[cg2 * 4 + 2], 0.f);
            o.w = fmaxf(acc2[i][3] + b2s[cg2 * 4 + 3], 0.f);
            *(float4*)&Hout[(size_t)r * 64 + cg2 * 4] = o;
        }
    }
}

// ---------------- 6) final: out = relu(relu(cat@P1 + bp1eff)@P2 + bp2) ----------------
__global__ void final_kernel(const float* __restrict__ P1, const float* __restrict__ P2,
                             const float* __restrict__ bp2, float* __restrict__ out) {
    extern __shared__ float sh[];
    float* As  = sh;                 // 64*64 (reloaded per chunk)
    float* P1s = As + 4096;          // 64*128 (per chunk)
    float* P2s = P1s + 8192;         // 128*64
    float* Ts  = P2s + 8192;         // 64*128
    float* be  = Ts + 8192;          // 128
    float* b2s = be + 128;           // 64

    int tid = threadIdx.x;
    int row0 = blockIdx.x * 64;

    {
        const float4* P24 = (const float4*)P2;
        float4* P2s4 = (float4*)P2s;
        #pragma unroll
        for (int idx = tid; idx < 2048; idx += 256) P2s4[idx] = P24[idx];
        if (tid < 128) be[tid] = g_bp1eff[tid];
        if (tid < 64)  b2s[tid] = bp2[tid];
    }

    int rg = tid >> 4;
    int cg = tid & 15;

    float acc[4][8];
    #pragma unroll
    for (int i = 0; i < 4; i++)
        #pragma unroll
        for (int j = 0; j < 8; j++) acc[i][j] = 0.f;

    for (int kb = 0; kb < 3; kb++) {
        __syncthreads();
        const float4* X4 = (const float4*)(g_h + (size_t)kb * NROI * CCH + (size_t)row0 * 64);
        float4* As4 = (float4*)As;
        #pragma unroll
        for (int idx = tid; idx < 1024; idx += 256) {
            int r = idx >> 4;
            As4[idx] = (row0 + r < NROI) ? X4[idx] : make_float4(0.f, 0.f, 0.f, 0.f);
        }
        const float4* P14 = (const float4*)(P1 + (size_t)kb * 64 * 128);
        float4* P1s4 = (float4*)P1s;
        #pragma unroll
        for (int idx = tid; idx < 2048; idx += 256) P1s4[idx] = P14[idx];
        __syncthreads();

        #pragma unroll 4
        for (int k = 0; k < 64; k++) {
            float a[4];
            #pragma unroll
            for (int i = 0; i < 4; i++) a[i] = As[(rg * 4 + i) * 64 + k];
            float4 w0 = *(const float4*)&P1s[k * 128 + cg * 8];
            float4 w1 = *(const float4*)&P1s[k * 128 + cg * 8 + 4];
            float wv[8] = {w0.x, w0.y, w0.z, w0.w, w1.x, w1.y, w1.z, w1.w};
            #pragma unroll
            for (int i = 0; i < 4; i++)
                #pragma unroll
                for (int j = 0; j < 8; j++)
                    acc[i][j] = fmaf(a[i], wv[j], acc[i][j]);
        }
    }

    #pragma unroll
    for (int i = 0; i < 4; i++) {
        int r = rg * 4 + i;
        #pragma unroll
        for (int j = 0; j < 8; j++)
            Ts[r * 128 + cg * 8 + j] = fmaxf(acc[i][j] + be[cg * 8 + j], 0.f);
    }
    __syncthreads();

    int cg2 = tid & 15;
    float acc2[4][4];
    #pragma unroll
    for (int i = 0; i < 4; i++)
        #pragma unroll
        for (int j = 0; j < 4; j++) acc2[i][j] = 0.f;

    #pragma unroll 4
    for (int k = 0; k < 128; k++) {
        float a[4];
        #pragma unroll
        for (int i = 0; i < 4; i++) a[i] = Ts[(rg * 4 + i) * 128 + k];
        float4 w = *(const float4*)&P2s[k * 64 + cg2 * 4];
        float wv[4] = {w.x, w.y, w.z, w.w};
        #pragma unroll
        for (int i = 0; i < 4; i++)
            #pragma unroll
            for (int j = 0; j < 4; j++)
                acc2[i][j] = fmaf(a[i], wv[j], acc2[i][j]);
    }
    #pragma unroll
    for (int i = 0; i < 4; i++) {
        int r = row0 + rg * 4 + i;
        if (r < NROI) {
            float4 o;
            o.x = fmaxf(acc2[i][0] + b2s[cg2 * 4 + 0], 0.f);
            o.y = fmaxf(acc2[i][1] + b2s[cg2 * 4 + 1], 0.f);
            o.z = fmaxf(acc2[i][2] + b2s[cg2 * 4 + 2], 0.f);
            o.w = fmaxf(acc2[i][3] + b2s[cg2 * 4 + 3], 0.f);
            *(float4*)&out[(size_t)r * 64 + cg2 * 4] = o;
        }
    }
}

// ---------------- launch ----------------
extern "C" void kernel_launch(void* const* d_in, const int* in_sizes, int n_in,
                              void* d_out, int out_size) {
    const float* fm    = (const float*)d_in[0];
    const float* boxes = (const float*)d_in[1];
    const float* W1    = (const float*)d_in[2];
    const float* b1    = (const float*)d_in[3];
    const float* W2    = (const float*)d_in[4];
    const float* b2    = (const float*)d_in[5];
    const float* P1    = (const float*)d_in[6];
    const float* bp1   = (const float*)d_in[7];
    const float* P2    = (const float*)d_in[8];
    const float* bp2   = (const float*)d_in[9];
    float* out = (float*)d_out;

    const int SMEM = (4096 + 8192 + 8192 + 8192 + 128 + 64) * 4;  // 115456 B
    cudaFuncSetAttribute(head_kernel,  cudaFuncAttributeMaxDynamicSharedMemorySize, SMEM);
    cudaFuncSetAttribute(final_kernel, cudaFuncAttributeMaxDynamicSharedMemorySize, SMEM);

    transpose_kernel<<<NPIX / 64, 256>>>(fm);
    gmean_kernel<<<64, 256>>>(fm);
    head_const_kernel<<<1, 128>>>(W1, b1, W2, b2, P1, bp1);

    pool_kernel<3><<<NROI, 256>>>(boxes, 0);
    pool_kernel<7><<<NROI, 256>>>(boxes, 1);
    pool_kernel<11><<<NROI, 256>>>(boxes, 2);

    const int NT = (NROI + 63) / 64;  // 63 row tiles
    dim3 hgrid(NT, 3);
    head_kernel<<<hgrid, 256, SMEM>>>(W1, b1, W2, b2);
    final_kernel<<<NT, 256, SMEM>>>(P1, P2, bp2, out);
}

// round 3
// speedup vs baseline: 1.6375x; 1.0268x over previous
#include <cuda_runtime.h>
#include <cuda_fp16.h>

#define NROI 4000
#define CCH  64
#define FH   240
#define FW   240
#define NPIX (FH*FW)

// ---------------- scratch (no allocations allowed) ----------------
__device__ __half2 g_fmTh[NPIX * 32];      // HWC fp16 feature map (7.4 MB), 32 half2 = 64ch
__device__ float g_pooled[3 * NROI * CCH]; // pooled features per scale
__device__ float g_h[3 * NROI * CCH];      // head outputs per scale
__device__ float g_gmean[CCH];             // global mean per channel
__device__ float g_bp1eff[128];            // bp1 + head(g) @ P1[192:256]

// ---------------- 1) transpose CHW fp32 -> HWC fp16 (half2 packed) ----------------
__global__ void transpose_kernel(const float* __restrict__ fm) {
    __shared__ float tile[64][65];
    int pix0 = blockIdx.x * 64;
    int tid  = threadIdx.x;
    int lane = tid & 63;     // pixel offset on load
    int grp  = tid >> 6;     // 0..3
    #pragma unroll
    for (int c = grp; c < 64; c += 4)
        tile[c][lane] = fm[c * NPIX + pix0 + lane];
    __syncthreads();
    int c2 = tid & 31;       // channel pair
    int pg = tid >> 5;       // 0..7
    #pragma unroll
    for (int p = pg; p < 64; p += 8)
        g_fmTh[(pix0 + p) * 32 + c2] =
            __floats2half2_rn(tile[2 * c2][p], tile[2 * c2 + 1][p]);
}

// ---------------- 2) global channel mean (fp32 source) ----------------
__global__ void gmean_kernel(const float* __restrict__ fm) {
    int ch = blockIdx.x, tid = threadIdx.x;
    const float* p = fm + ch * NPIX;
    float s = 0.f;
    for (int i = tid; i < NPIX; i += 256) s += p[i];
    __shared__ float sm[256];
    sm[tid] = s;
    __syncthreads();
    for (int off = 128; off; off >>= 1) {
        if (tid < off) sm[tid] += sm[tid + off];
        __syncthreads();
    }
    if (tid == 0) g_gmean[ch] = sm[0] * (1.0f / (float)NPIX);
}

// ---------------- 3) head(g) folded into bp1 ----------------
__global__ void head_const_kernel(const float* __restrict__ W1, const float* __restrict__ b1,
                                  const float* __restrict__ W2, const float* __restrict__ b2,
                                  const float* __restrict__ P1, const float* __restrict__ bp1) {
    __shared__ float gs[64];
    __shared__ float t[128];
    __shared__ float hg[64];
    int tid = threadIdx.x;  // 128 threads
    if (tid < 64) gs[tid] = g_gmean[tid];
    __syncthreads();
    float a = b1[tid];
    #pragma unroll 8
    for (int c = 0; c < 64; c++) a = fmaf(gs[c], W1[c * 128 + tid], a);
    t[tid] = fmaxf(a, 0.f);
    __syncthreads();
    if (tid < 64) {
        float a2 = b2[tid];
        #pragma unroll 8
        for (int k = 0; k < 128; k++) a2 = fmaf(t[k], W2[k * 64 + tid], a2);
        hg[tid] = fmaxf(a2, 0.f);
    }
    __syncthreads();
    float be = bp1[tid];
    #pragma unroll 8
    for (int c = 0; c < 64; c++) be = fmaf(hg[c], P1[(192 + c) * 128 + tid], be);
    g_bp1eff[tid] = be;
}

// ---------------- 4) bilinear ROI average pooling: warp-per-ROI ----------------
template<int S>
__global__ void pool_kernel(const float* __restrict__ boxes, int scale) {
    constexpr int SS = S * S;
    int tid  = threadIdx.x;
    int lane = tid & 31;     // channel pair 2*lane, 2*lane+1
    int warp = tid >> 5;     // 0..7
    int n = blockIdx.x * 8 + warp;
    if (n >= NROI) return;

    float bx1 = __ldg(&boxes[n * 4 + 0]);
    float by1 = __ldg(&boxes[n * 4 + 1]);
    float bx2 = __ldg(&boxes[n * 4 + 2]);
    float by2 = __ldg(&boxes[n * 4 + 3]);
    float nx1 = bx1 * (2.0f / 960.0f) - 1.0f;
    float ny1 = by1 * (2.0f / 960.0f) - 1.0f;
    float nx2 = bx2 * (2.0f / 960.0f) - 1.0f;
    float ny2 = by2 * (2.0f / 960.0f) - 1.0f;
    float cx = (nx1 + nx2) * 0.5f;
    float cy = (ny1 + ny2) * 0.5f;
    float w  = fmaxf(nx2 - nx1, 1e-6f);
    float h  = fmaxf(ny2 - ny1, 1e-6f);
    // ix(j) = j*stepx + ixb ; iy(i) = i*stepy + iyb  (image-space sample coords)
    float stepx = w * (120.0f / (float)S);
    float stepy = h * (120.0f / (float)S);
    float ixb = fmaf(w * 60.0f, (1.0f / (float)S - 1.0f), fmaf(cx, 120.0f, 119.5f));
    float iyb = fmaf(h * 60.0f, (1.0f / (float)S - 1.0f), fmaf(cy, 120.0f, 119.5f));

    float accx = 0.f, accy = 0.f;
    float fj = 0.f, fi = 0.f;
    #pragma unroll 2
    for (int samp = 0; samp < SS; samp++) {
        float ix = fmaf(fj, stepx, ixb);
        float iy = fmaf(fi, stepy, iyb);
        float x0f = floorf(ix), y0f = floorf(iy);
        float dx = ix - x0f, dy = iy - y0f;
        int x0 = (int)x0f, y0 = (int)y0f;
        int x1 = x0 + 1,   y1 = y0 + 1;
        float wx0 = ((unsigned)x0 < FW) ? (1.f - dx) : 0.f;
        float wx1 = ((unsigned)x1 < FW) ? dx : 0.f;
        float wy0 = ((unsigned)y0 < FH) ? (1.f - dy) : 0.f;
        float wy1 = ((unsigned)y1 < FH) ? dy : 0.f;
        int xc0 = max(0, min(x0, FW - 1));
        int xc1 = max(0, min(x1, FW - 1));
        int yc0 = max(0, min(y0, FH - 1));
        int yc1 = max(0, min(y1, FH - 1));
        const __half2* r0 = g_fmTh + (yc0 * FW) * 32 + lane;
        const __half2* r1 = g_fmTh + (yc1 * FW) * 32 + lane;
        float2 f00 = __half22float2(r0[xc0 * 32]);
        float2 f01 = __half22float2(r0[xc1 * 32]);
        float2 f10 = __half22float2(r1[xc0 * 32]);
        float2 f11 = __half22float2(r1[xc1 * 32]);
        float tx = fmaf(f00.x, wx0, f01.x * wx1);
        float ty = fmaf(f00.y, wx0, f01.y * wx1);
        float bx = fmaf(f10.x, wx0, f11.x * wx1);
        float by = fmaf(f10.y, wx0, f11.y * wx1);
        accx = fmaf(wy0, tx, fmaf(wy1, bx, accx));
        accy = fmaf(wy0, ty, fmaf(wy1, by, accy));
        // advance (i,j)
        fj += 1.f;
        if (fj == (float)S) { fj = 0.f; fi += 1.f; }
    }

    float2* outp = (float2*)&g_pooled[((size_t)scale * NROI + n) * 64 + 2 * lane];
    *outp = make_float2(accx * (1.0f / (float)SS), accy * (1.0f / (float)SS));
}

// ---------------- 5) per-scale MLP head: relu(relu(X@W1+b1)@W2+b2) ----------------
__global__ void head_kernel(const float* __restrict__ W1, const float* __restrict__ b1,
                            const float* __restrict__ W2, const float* __restrict__ b2) {
    extern __shared__ float sh[];
    float* As  = sh;                 // 64*64
    float* W1s = As + 4096;          // 64*128
    float* W2s = W1s + 8192;         // 128*64
    float* Ts  = W2s + 8192;         // 64*128
    float* b1s = Ts + 8192;          // 128
    float* b2s = b1s + 128;          // 64

    int tid = threadIdx.x;
    int scale = blockIdx.y;
    int row0 = blockIdx.x * 64;
    const float* X    = g_pooled + (size_t)scale * NROI * CCH;
    float*       Hout = g_h      + (size_t)scale * NROI * CCH;

    {
        const float4* X4 = (const float4*)(X + (size_t)row0 * 64);
        float4* As4 = (float4*)As;
        #pragma unroll
        for (int idx = tid; idx < 1024; idx += 256) {
            int r = idx >> 4;
            As4[idx] = (row0 + r < NROI) ? X4[idx] : make_float4(0.f, 0.f, 0.f, 0.f);
        }
        const float4* W14 = (const float4*)W1;
        float4* W1s4 = (float4*)W1s;
        #pragma unroll
        for (int idx = tid; idx < 2048; idx += 256) W1s4[idx] = W14[idx];
        const float4* W24 = (const float4*)W2;
        float4* W2s4 = (float4*)W2s;
        #pragma unroll
        for (int idx = tid; idx < 2048; idx += 256) W2s4[idx] = W24[idx];
        if (tid < 128) b1s[tid] = b1[tid];
        if (tid < 64)  b2s[tid] = b2[tid];
    }
    __syncthreads();

    int rg = tid >> 4;
    int cg = tid & 15;

    float acc[4][8];
    #pragma unroll
    for (int i = 0; i < 4; i++)
        #pragma unroll
        for (int j = 0; j < 8; j++) acc[i][j] = 0.f;

    #pragma unroll 4
    for (int k = 0; k < 64; k++) {
        float a[4];
        #pragma unroll
        for (int i = 0; i < 4; i++) a[i] = As[(rg * 4 + i) * 64 + k];
        float4 w0 = *(const float4*)&W1s[k * 128 + cg * 8];
        float4 w1 = *(const float4*)&W1s[k * 128 + cg * 8 + 4];
        float wv[8] = {w0.x, w0.y, w0.z, w0.w, w1.x, w1.y, w1.z, w1.w};
        #pragma unroll
        for (int i = 0; i < 4; i++)
            #pragma unroll
            for (int j = 0; j < 8; j++)
                acc[i][j] = fmaf(a[i], wv[j], acc[i][j]);
    }
    #pragma unroll
    for (int i = 0; i < 4; i++) {
        int r = rg * 4 + i;
        #pragma unroll
        for (int j = 0; j < 8; j++)
            Ts[r * 128 + cg * 8 + j] = fmaxf(acc[i][j] + b1s[cg * 8 + j], 0.f);
    }
    __syncthreads();

    int cg2 = tid & 15;
    float acc2[4][4];
    #pragma unroll
    for (int i = 0; i < 4; i++)
        #pragma unroll
        for (int j = 0; j < 4; j++) acc2[i][j] = 0.f;

    #pragma unroll 4
    for (int k = 0; k < 128; k++) {
        float a[4];
        #pragma unroll
        for (int i = 0; i < 4; i++) a[i] = Ts[(rg * 4 + i) * 128 + k];
        float4 w = *(const float4*)&W2s[k * 64 + cg2 * 4];
        float wv[4] = {w.x, w.y, w.z, w.w};
        #pragma unroll
        for (int i = 0; i < 4; i++)
            #pragma unroll
            for (int j = 0; j < 4; j++)
                acc2[i][j] = fmaf(a[i], wv[j], acc2[i][j]);
    }
    #pragma unroll
    for (int i = 0; i < 4; i++) {
        int r = row0 + rg * 4 + i;
        if (r < NROI) {
            float4 o;
            o.x = fmaxf(acc2[i][0] + b2s[cg2 * 4 + 0], 0.f);
            o.y = fmaxf(acc2[i][1] + b2s[cg2 * 4 + 1], 0.f);
            o.z = fmaxf(acc2[i][2] + b2s[cg2 * 4 + 2], 0.f);
            o.w = fmaxf(acc2[i][3] + b2s[cg2 * 4 + 3], 0.f);
            *(float4*)&Hout[(size_t)r * 64 + cg2 * 4] = o;
        }
    }
}

// ---------------- 6) final: out = relu(relu(cat@P1 + bp1eff)@P2 + bp2) ----------------
__global__ void final_kernel(const float* __restrict__ P1, const float* __restrict__ P2,
                             const float* __restrict__ bp2, float* __restrict__ out) {
    extern __shared__ float sh[];
    float* As  = sh;                 // 64*64 (reloaded per chunk)
    float* P1s = As + 4096;          // 64*128 (per chunk)
    float* P2s = P1s + 8192;         // 128*64
    float* Ts  = P2s + 8192;         // 64*128
    float* be  = Ts + 8192;          // 128
    float* b2s = be + 128;           // 64

    int tid = threadIdx.x;
    int row0 = blockIdx.x * 64;

    {
        const float4* P24 = (const float4*)P2;
        float4* P2s4 = (float4*)P2s;
        #pragma unroll
        for (int idx = tid; idx < 2048; idx += 256) P2s4[idx] = P24[idx];
        if (tid < 128) be[tid] = g_bp1eff[tid];
        if (tid < 64)  b2s[tid] = bp2[tid];
    }

    int rg = tid >> 4;
    int cg = tid & 15;

    float acc[4][8];
    #pragma unroll
    for (int i = 0; i < 4; i++)
        #pragma unroll
        for (int j = 0; j < 8; j++) acc[i][j] = 0.f;

    for (int kb = 0; kb < 3; kb++) {
        __syncthreads();
        const float4* X4 = (const float4*)(g_h + (size_t)kb * NROI * CCH + (size_t)row0 * 64);
        float4* As4 = (float4*)As;
        #pragma unroll
        for (int idx = tid; idx < 1024; idx += 256) {
            int r = idx >> 4;
            As4[idx] = (row0 + r < NROI) ? X4[idx] : make_float4(0.f, 0.f, 0.f, 0.f);
        }
        const float4* P14 = (const float4*)(P1 + (size_t)kb * 64 * 128);
        float4* P1s4 = (float4*)P1s;
        #pragma unroll
        for (int idx = tid; idx < 2048; idx += 256) P1s4[idx] = P14[idx];
        __syncthreads();

        #pragma unroll 4
        for (int k = 0; k < 64; k++) {
            float a[4];
            #pragma unroll
            for (int i = 0; i < 4; i++) a[i] = As[(rg * 4 + i) * 64 + k];
            float4 w0 = *(const float4*)&P1s[k * 128 + cg * 8];
            float4 w1 = *(const float4*)&P1s[k * 128 + cg * 8 + 4];
            float wv[8] = {w0.x, w0.y, w0.z, w0.w, w1.x, w1.y, w1.z, w1.w};
            #pragma unroll
            for (int i = 0; i < 4; i++)
                #pragma unroll
                for (int j = 0; j < 8; j++)
                    acc[i][j] = fmaf(a[i], wv[j], acc[i][j]);
        }
    }

    #pragma unroll
    for (int i = 0; i < 4; i++) {
        int r = rg * 4 + i;
        #pragma unroll
        for (int j = 0; j < 8; j++)
            Ts[r * 128 + cg * 8 + j] = fmaxf(acc[i][j] + be[cg * 8 + j], 0.f);
    }
    __syncthreads();

    int cg2 = tid & 15;
    float acc2[4][4];
    #pragma unroll
    for (int i = 0; i < 4; i++)
        #pragma unroll
        for (int j = 0; j < 4; j++) acc2[i][j] = 0.f;

    #pragma unroll 4
    for (int k = 0; k < 128; k++) {
        float a[4];
        #pragma unroll
        for (int i = 0; i < 4; i++) a[i] = Ts[(rg * 4 + i) * 128 + k];
        float4 w = *(const float4*)&P2s[k * 64 + cg2 * 4];
        float wv[4] = {w.x, w.y, w.z, w.w};
        #pragma unroll
        for (int i = 0; i < 4; i++)
            #pragma unroll
            for (int j = 0; j < 4; j++)
                acc2[i][j] = fmaf(a[i], wv[j], acc2[i][j]);
    }
    #pragma unroll
    for (int i = 0; i < 4; i++) {
        int r = row0 + rg * 4 + i;
        if (r < NROI) {
            float4 o;
            o.x = fmaxf(acc2[i][0] + b2s[cg2 * 4 + 0], 0.f);
            o.y = fmaxf(acc2[i][1] + b2s[cg2 * 4 + 1], 0.f);
            o.z = fmaxf(acc2[i][2] + b2s[cg2 * 4 + 2], 0.f);
            o.w = fmaxf(acc2[i][3] + b2s[cg2 * 4 + 3], 0.f);
            *(float4*)&out[(size_t)r * 64 + cg2 * 4] = o;
        }
    }
}

// ---------------- launch ----------------
extern "C" void kernel_launch(void* const* d_in, const int* in_sizes, int n_in,
                              void* d_out, int out_size) {
    const float* fm    = (const float*)d_in[0];
    const float* boxes = (const float*)d_in[1];
    const float* W1    = (const float*)d_in[2];
    const float* b1    = (const float*)d_in[3];
    const float* W2    = (const float*)d_in[4];
    const float* b2    = (const float*)d_in[5];
    const float* P1    = (const float*)d_in[6];
    const float* bp1   = (const float*)d_in[7];
    const float* P2    = (const float*)d_in[8];
    const float* bp2   = (const float*)d_in[9];
    float* out = (float*)d_out;

    const int SMEM = (4096 + 8192 + 8192 + 8192 + 128 + 64) * 4;  // 115456 B
    cudaFuncSetAttribute(head_kernel,  cudaFuncAttributeMaxDynamicSharedMemorySize, SMEM);
    cudaFuncSetAttribute(final_kernel, cudaFuncAttributeMaxDynamicSharedMemorySize, SMEM);

    transpose_kernel<<<NPIX / 64, 256>>>(fm);
    gmean_kernel<<<64, 256>>>(fm);
    head_const_kernel<<<1, 128>>>(W1, b1, W2, b2, P1, bp1);

    const int PB = (NROI + 7) / 8;  // 500 blocks, 8 warps = 8 ROIs each
    pool_kernel<3><<<PB, 256>>>(boxes, 0);
    pool_kernel<7><<<PB, 256>>>(boxes, 1);
    pool_kernel<11><<<PB, 256>>>(boxes, 2);

    const int NT = (NROI + 63) / 64;  // 63 row tiles
    dim3 hgrid(NT, 3);
    head_kernel<<<hgrid, 256, SMEM>>>(W1, b1, W2, b2);
    final_kernel<<<NT, 256, SMEM>>>(P1, P2, bp2, out);
}

// round 4
// speedup vs baseline: 1.8084x; 1.1044x over previous
#include <cuda_runtime.h>
#include <cuda_fp16.h>

#define NROI 4000
#define CCH  64
#define FH   240
#define FW   240
#define NPIX (FH*FW)

// ---------------- scratch (no allocations allowed) ----------------
__device__ __half2 g_fmTh[NPIX * 32];      // HWC fp16 feature map (7.4 MB), 32 half2 = 64ch
__device__ float g_pooled[3 * NROI * CCH]; // pooled features per scale
__device__ float g_h[3 * NROI * CCH];      // head outputs per scale
__device__ float g_gmean[CCH];             // global mean per channel
__device__ float g_bp1eff[128];            // bp1 + head(g) @ P1[192:256]

// ---------------- 1) transpose CHW fp32 -> HWC fp16 (half2 packed) ----------------
__global__ void transpose_kernel(const float* __restrict__ fm) {
    __shared__ float tile[64][65];
    int pix0 = blockIdx.x * 64;
    int tid  = threadIdx.x;
    int lane = tid & 63;     // pixel offset on load
    int grp  = tid >> 6;     // 0..3
    #pragma unroll
    for (int c = grp; c < 64; c += 4)
        tile[c][lane] = fm[c * NPIX + pix0 + lane];
    __syncthreads();
    int c2 = tid & 31;       // channel pair
    int pg = tid >> 5;       // 0..7
    #pragma unroll
    for (int p = pg; p < 64; p += 8)
        g_fmTh[(pix0 + p) * 32 + c2] =
            __floats2half2_rn(tile[2 * c2][p], tile[2 * c2 + 1][p]);
}

// ---------------- 2) global channel mean (fp32 source) ----------------
__global__ void gmean_kernel(const float* __restrict__ fm) {
    int ch = blockIdx.x, tid = threadIdx.x;
    const float* p = fm + ch * NPIX;
    float s = 0.f;
    for (int i = tid; i < NPIX; i += 256) s += p[i];
    __shared__ float sm[256];
    sm[tid] = s;
    __syncthreads();
    for (int off = 128; off; off >>= 1) {
        if (tid < off) sm[tid] += sm[tid + off];
        __syncthreads();
    }
    if (tid == 0) g_gmean[ch] = sm[0] * (1.0f / (float)NPIX);
}

// ---------------- 3) head(g) folded into bp1 ----------------
__global__ void head_const_kernel(const float* __restrict__ W1, const float* __restrict__ b1,
                                  const float* __restrict__ W2, const float* __restrict__ b2,
                                  const float* __restrict__ P1, const float* __restrict__ bp1) {
    __shared__ float gs[64];
    __shared__ float t[128];
    __shared__ float hg[64];
    int tid = threadIdx.x;  // 128 threads
    if (tid < 64) gs[tid] = g_gmean[tid];
    __syncthreads();
    float a = b1[tid];
    #pragma unroll 8
    for (int c = 0; c < 64; c++) a = fmaf(gs[c], W1[c * 128 + tid], a);
    t[tid] = fmaxf(a, 0.f);
    __syncthreads();
    if (tid < 64) {
        float a2 = b2[tid];
        #pragma unroll 8
        for (int k = 0; k < 128; k++) a2 = fmaf(t[k], W2[k * 64 + tid], a2);
        hg[tid] = fmaxf(a2, 0.f);
    }
    __syncthreads();
    float be = bp1[tid];
    #pragma unroll 8
    for (int c = 0; c < 64; c++) be = fmaf(hg[c], P1[(192 + c) * 128 + tid], be);
    g_bp1eff[tid] = be;
}

// ---------------- 4) bilinear ROI pooling: fused warp-per-(roi,scale) ----------------
template<int S>
__device__ __forceinline__ void pool_roi(int n, int lane,
                                         const float* __restrict__ boxes,
                                         float* __restrict__ outb) {
    constexpr int SS = S * S;
    float bx1 = __ldg(&boxes[n * 4 + 0]);
    float by1 = __ldg(&boxes[n * 4 + 1]);
    float bx2 = __ldg(&boxes[n * 4 + 2]);
    float by2 = __ldg(&boxes[n * 4 + 3]);
    float nx1 = bx1 * (2.0f / 960.0f) - 1.0f;
    float ny1 = by1 * (2.0f / 960.0f) - 1.0f;
    float nx2 = bx2 * (2.0f / 960.0f) - 1.0f;
    float ny2 = by2 * (2.0f / 960.0f) - 1.0f;
    float cx = (nx1 + nx2) * 0.5f;
    float cy = (ny1 + ny2) * 0.5f;
    float w  = fmaxf(nx2 - nx1, 1e-6f);
    float h  = fmaxf(ny2 - ny1, 1e-6f);
    float stepx = w * (120.0f / (float)S);
    float stepy = h * (120.0f / (float)S);
    float ixb = fmaf(w * 60.0f, (1.0f / (float)S - 1.0f), fmaf(cx, 120.0f, 119.5f));
    float iyb = fmaf(h * 60.0f, (1.0f / (float)S - 1.0f), fmaf(cy, 120.0f, 119.5f));

    float accx = 0.f, accy = 0.f;
    float fj = 0.f, fi = 0.f;
    #pragma unroll 2
    for (int samp = 0; samp < SS; samp++) {
        float ix = fmaf(fj, stepx, ixb);
        float iy = fmaf(fi, stepy, iyb);
        float x0f = floorf(ix), y0f = floorf(iy);
        float dx = ix - x0f, dy = iy - y0f;
        int x0 = (int)x0f, y0 = (int)y0f;
        int x1 = x0 + 1,   y1 = y0 + 1;
        float wx0 = ((unsigned)x0 < FW) ? (1.f - dx) : 0.f;
        float wx1 = ((unsigned)x1 < FW) ? dx : 0.f;
        float wy0 = ((unsigned)y0 < FH) ? (1.f - dy) : 0.f;
        float wy1 = ((unsigned)y1 < FH) ? dy : 0.f;
        int xc0 = max(0, min(x0, FW - 1));
        int xc1 = max(0, min(x1, FW - 1));
        int yc0 = max(0, min(y0, FH - 1));
        int yc1 = max(0, min(y1, FH - 1));
        const __half2* r0 = g_fmTh + (yc0 * FW) * 32 + lane;
        const __half2* r1 = g_fmTh + (yc1 * FW) * 32 + lane;
        float2 f00 = __half22float2(r0[xc0 * 32]);
        float2 f01 = __half22float2(r0[xc1 * 32]);
        float2 f10 = __half22float2(r1[xc0 * 32]);
        float2 f11 = __half22float2(r1[xc1 * 32]);
        float tx = fmaf(f00.x, wx0, f01.x * wx1);
        float ty = fmaf(f00.y, wx0, f01.y * wx1);
        float bx = fmaf(f10.x, wx0, f11.x * wx1);
        float by = fmaf(f10.y, wx0, f11.y * wx1);
        accx = fmaf(wy0, tx, fmaf(wy1, bx, accx));
        accy = fmaf(wy0, ty, fmaf(wy1, by, accy));
        fj += 1.f;
        if (fj == (float)S) { fj = 0.f; fi += 1.f; }
    }
    float2* outp = (float2*)&outb[(size_t)n * 64 + 2 * lane];
    *outp = make_float2(accx * (1.0f / (float)SS), accy * (1.0f / (float)SS));
}

__global__ void pool_all_kernel(const float* __restrict__ boxes) {
    int tid  = threadIdx.x;
    int lane = tid & 31;
    int warp = tid >> 5;
    int task = blockIdx.x * 8 + warp;     // 0..11999, scale-major
    if (task >= 3 * NROI) return;
    if (task < NROI) {
        pool_roi<3>(task, lane, boxes, g_pooled);
    } else if (task < 2 * NROI) {
        pool_roi<7>(task - NROI, lane, boxes, g_pooled + (size_t)NROI * CCH);
    } else {
        pool_roi<11>(task - 2 * NROI, lane, boxes, g_pooled + (size_t)2 * NROI * CCH);
    }
}

// ---------------- 5) per-scale MLP head: relu(relu(X@W1+b1)@W2+b2) ----------------
__global__ void head_kernel(const float* __restrict__ W1, const float* __restrict__ b1,
                            const float* __restrict__ W2, const float* __restrict__ b2) {
    extern __shared__ float sh[];
    float* As  = sh;                 // 64*64
    float* W1s = As + 4096;          // 64*128
    float* W2s = W1s + 8192;         // 128*64
    float* Ts  = W2s + 8192;         // 64*128
    float* b1s = Ts + 8192;          // 128
    float* b2s = b1s + 128;          // 64

    int tid = threadIdx.x;
    int scale = blockIdx.y;
    int row0 = blockIdx.x * 64;
    const float* X    = g_pooled + (size_t)scale * NROI * CCH;
    float*       Hout = g_h      + (size_t)scale * NROI * CCH;

    {
        const float4* X4 = (const float4*)(X + (size_t)row0 * 64);
        float4* As4 = (float4*)As;
        #pragma unroll
        for (int idx = tid; idx < 1024; idx += 256) {
            int r = idx >> 4;
            As4[idx] = (row0 + r < NROI) ? X4[idx] : make_float4(0.f, 0.f, 0.f, 0.f);
        }
        const float4* W14 = (const float4*)W1;
        float4* W1s4 = (float4*)W1s;
        #pragma unroll
        for (int idx = tid; idx < 2048; idx += 256) W1s4[idx] = W14[idx];
        const float4* W24 = (const float4*)W2;
        float4* W2s4 = (float4*)W2s;
        #pragma unroll
        for (int idx = tid; idx < 2048; idx += 256) W2s4[idx] = W24[idx];
        if (tid < 128) b1s[tid] = b1[tid];
        if (tid < 64)  b2s[tid] = b2[tid];
    }
    __syncthreads();

    int rg = tid >> 4;
    int cg = tid & 15;

    float acc[4][8];
    #pragma unroll
    for (int i = 0; i < 4; i++)
        #pragma unroll
        for (int j = 0; j < 8; j++) acc[i][j] = 0.f;

    #pragma unroll 4
    for (int k = 0; k < 64; k++) {
        float a[4];
        #pragma unroll
        for (int i = 0; i < 4; i++) a[i] = As[(rg * 4 + i) * 64 + k];
        float4 w0 = *(const float4*)&W1s[k * 128 + cg * 8];
        float4 w1 = *(const float4*)&W1s[k * 128 + cg * 8 + 4];
        float wv[8] = {w0.x, w0.y, w0.z, w0.w, w1.x, w1.y, w1.z, w1.w};
        #pragma unroll
        for (int i = 0; i < 4; i++)
            #pragma unroll
            for (int j = 0; j < 8; j++)
                acc[i][j] = fmaf(a[i], wv[j], acc[i][j]);
    }
    #pragma unroll
    for (int i = 0; i < 4; i++) {
        int r = rg * 4 + i;
        #pragma unroll
        for (int j = 0; j < 8; j++)
            Ts[r * 128 + cg * 8 + j] = fmaxf(acc[i][j] + b1s[cg * 8 + j], 0.f);
    }
    __syncthreads();

    int cg2 = tid & 15;
    float acc2[4][4];
    #pragma unroll
    for (int i = 0; i < 4; i++)
        #pragma unroll
        for (int j = 0; j < 4; j++) acc2[i][j] = 0.f;

    #pragma unroll 4
    for (int k = 0; k < 128; k++) {
        float a[4];
        #pragma unroll
        for (int i = 0; i < 4; i++) a[i] = Ts[(rg * 4 + i) * 128 + k];
        float4 w = *(const float4*)&W2s[k * 64 + cg2 * 4];
        float wv[4] = {w.x, w.y, w.z, w.w};
        #pragma unroll
        for (int i = 0; i < 4; i++)
            #pragma unroll
            for (int j = 0; j < 4; j++)
                acc2[i][j] = fmaf(a[i], wv[j], acc2[i][j]);
    }
    #pragma unroll
    for (int i = 0; i < 4; i++) {
        int r = row0 + rg * 4 + i;
        if (r < NROI) {
            float4 o;
            o.x = fmaxf(acc2[i][0] + b2s[cg2 * 4 + 0], 0.f);
            o.y = fmaxf(acc2[i][1] + b2s[cg2 * 4 + 1], 0.f);
            o.z = fmaxf(acc2[i][2] + b2s[cg2 * 4 + 2], 0.f);
            o.w = fmaxf(acc2[i][3] + b2s[cg2 * 4 + 3], 0.f);
            *(float4*)&Hout[(size_t)r * 64 + cg2 * 4] = o;
        }
    }
}

// ---------------- 6) final: 32-row tiles, out = relu(relu(cat@P1+bp1eff)@P2+bp2) ----------------
__global__ void final_kernel(const float* __restrict__ P1, const float* __restrict__ P2,
                             const float* __restrict__ bp2, float* __restrict__ out) {
    extern __shared__ float sh[];
    float* As  = sh;                 // 32*64 (per chunk)
    float* P1s = As + 2048;          // 64*128 (per chunk)
    float* P2s = P1s + 8192;         // 128*64
    float* Ts  = P2s + 8192;         // 32*128
    float* be  = Ts + 4096;          // 128
    float* b2s = be + 128;           // 64

    int tid = threadIdx.x;
    int row0 = blockIdx.x * 32;

    {
        const float4* P24 = (const float4*)P2;
        float4* P2s4 = (float4*)P2s;
        #pragma unroll
        for (int idx = tid; idx < 2048; idx += 256) P2s4[idx] = P24[idx];
        if (tid < 128) be[tid] = g_bp1eff[tid];
        if (tid < 64)  b2s[tid] = bp2[tid];
    }

    int rg = tid >> 4;   // 0..15 -> rows rg*2, rg*2+1
    int cg = tid & 15;   // cols cg*8..+7

    float acc[2][8];
    #pragma unroll
    for (int i = 0; i < 2; i++)
        #pragma unroll
        for (int j = 0; j < 8; j++) acc[i][j] = 0.f;

    for (int kb = 0; kb < 3; kb++) {
        __syncthreads();
        const float4* X4 = (const float4*)(g_h + (size_t)kb * NROI * CCH + (size_t)row0 * 64);
        float4* As4 = (float4*)As;
        #pragma unroll
        for (int idx = tid; idx < 512; idx += 256) {
            int r = idx >> 4;
            As4[idx] = (row0 + r < NROI) ? X4[idx] : make_float4(0.f, 0.f, 0.f, 0.f);
        }
        const float4* P14 = (const float4*)(P1 + (size_t)kb * 64 * 128);
        float4* P1s4 = (float4*)P1s;
        #pragma unroll
        for (int idx = tid; idx < 2048; idx += 256) P1s4[idx] = P14[idx];
        __syncthreads();

        #pragma unroll 4
        for (int k = 0; k < 64; k++) {
            float a[2];
            #pragma unroll
            for (int i = 0; i < 2; i++) a[i] = As[(rg * 2 + i) * 64 + k];
            float4 w0 = *(const float4*)&P1s[k * 128 + cg * 8];
            float4 w1 = *(const float4*)&P1s[k * 128 + cg * 8 + 4];
            float wv[8] = {w0.x, w0.y, w0.z, w0.w, w1.x, w1.y, w1.z, w1.w};
            #pragma unroll
            for (int i = 0; i < 2; i++)
                #pragma unroll
                for (int j = 0; j < 8; j++)
                    acc[i][j] = fmaf(a[i], wv[j], acc[i][j]);
        }
    }

    #pragma unroll
    for (int i = 0; i < 2; i++) {
        int r = rg * 2 + i;
        #pragma unroll
        for (int j = 0; j < 8; j++)
            Ts[r * 128 + cg * 8 + j] = fmaxf(acc[i][j] + be[cg * 8 + j], 0.f);
    }
    __syncthreads();

    int cg2 = tid & 15;
    float acc2[2][4];
    #pragma unroll
    for (int i = 0; i < 2; i++)
        #pragma unroll
        for (int j = 0; j < 4; j++) acc2[i][j] = 0.f;

    #pragma unroll 4
    for (int k = 0; k < 128; k++) {
        float a[2];
        #pragma unroll
        for (int i = 0; i < 2; i++) a[i] = Ts[(rg * 2 + i) * 128 + k];
        float4 w = *(const float4*)&P2s[k * 64 + cg2 * 4];
        float wv[4] = {w.x, w.y, w.z, w.w};
        #pragma unroll
        for (int i = 0; i < 2; i++)
            #pragma unroll
            for (int j = 0; j < 4; j++)
                acc2[i][j] = fmaf(a[i], wv[j], acc2[i][j]);
    }
    #pragma unroll
    for (int i = 0; i < 2; i++) {
        int r = row0 + rg * 2 + i;
        if (r < NROI) {
            float4 o;
            o.x = fmaxf(acc2[i][0] + b2s[cg2 * 4 + 0], 0.f);
            o.y = fmaxf(acc2[i][1] + b2s[cg2 * 4 + 1], 0.f);
            o.z = fmaxf(acc2[i][2] + b2s[cg2 * 4 + 2], 0.f);
            o.w = fmaxf(acc2[i][3] + b2s[cg2 * 4 + 3], 0.f);
            *(float4*)&out[(size_t)r * 64 + cg2 * 4] = o;
        }
    }
}

// ---------------- launch ----------------
extern "C" void kernel_launch(void* const* d_in, const int* in_sizes, int n_in,
                              void* d_out, int out_size) {
    const float* fm    = (const float*)d_in[0];
    const float* boxes = (const float*)d_in[1];
    const float* W1    = (const float*)d_in[2];
    const float* b1    = (const float*)d_in[3];
    const float* W2    = (const float*)d_in[4];
    const float* b2    = (const float*)d_in[5];
    const float* P1    = (const float*)d_in[6];
    const float* bp1   = (const float*)d_in[7];
    const float* P2    = (const float*)d_in[8];
    const float* bp2   = (const float*)d_in[9];
    float* out = (float*)d_out;

    const int SMEM_H = (4096 + 8192 + 8192 + 8192 + 128 + 64) * 4;
    const int SMEM_F = (2048 + 8192 + 8192 + 4096 + 128 + 64) * 4;
    cudaFuncSetAttribute(head_kernel,  cudaFuncAttributeMaxDynamicSharedMemorySize, SMEM_H);
    cudaFuncSetAttribute(final_kernel, cudaFuncAttributeMaxDynamicSharedMemorySize, SMEM_F);

    transpose_kernel<<<NPIX / 64, 256>>>(fm);
    gmean_kernel<<<64, 256>>>(fm);
    head_const_kernel<<<1, 128>>>(W1, b1, W2, b2, P1, bp1);

    const int PB = (3 * NROI + 7) / 8;  // 1500 blocks, 8 warps each
    pool_all_kernel<<<PB, 256>>>(boxes);

    const int NT = (NROI + 63) / 64;    // 63 row tiles
    dim3 hgrid(NT, 3);
    head_kernel<<<hgrid, 256, SMEM_H>>>(W1, b1, W2, b2);

    const int NT2 = (NROI + 31) / 32;   // 125 row tiles
    final_kernel<<<NT2, 256, SMEM_F>>>(P1, P2, bp2, out);
}

// round 5
// speedup vs baseline: 2.5073x; 1.3864x over previous
#include <cuda_runtime.h>
#include <cuda_fp16.h>

#define NROI 4000
#define CCH  64
#define FH   240
#define FW   240
#define NPIX (FH*FW)

// ---------------- scratch (no allocations allowed) ----------------
__device__ __align__(16) __half2 g_fmTh[NPIX * 32]; // HWC fp16 fm (7.4 MB), 32 half2 = 64ch
__device__ float g_pooled[3 * NROI * CCH]; // pooled features per scale
__device__ float g_h[3 * NROI * CCH];      // head outputs per scale
__device__ float g_gmean[CCH];             // global mean per channel
__device__ float g_bp1eff[128];            // bp1 + head(g) @ P1[192:256]

// ---------------- 1) transpose CHW fp32 -> HWC fp16 (half2 packed) ----------------
__global__ void transpose_kernel(const float* __restrict__ fm) {
    __shared__ float tile[64][65];
    int pix0 = blockIdx.x * 64;
    int tid  = threadIdx.x;
    int lane = tid & 63;     // pixel offset on load
    int grp  = tid >> 6;     // 0..3
    #pragma unroll
    for (int c = grp; c < 64; c += 4)
        tile[c][lane] = fm[c * NPIX + pix0 + lane];
    __syncthreads();
    int c2 = tid & 31;       // channel pair
    int pg = tid >> 5;       // 0..7
    #pragma unroll
    for (int p = pg; p < 64; p += 8)
        g_fmTh[(pix0 + p) * 32 + c2] =
            __floats2half2_rn(tile[2 * c2][p], tile[2 * c2 + 1][p]);
}

// ---------------- 2) global channel mean (fp32 source) ----------------
__global__ void gmean_kernel(const float* __restrict__ fm) {
    int ch = blockIdx.x, tid = threadIdx.x;
    const float* p = fm + ch * NPIX;
    float s = 0.f;
    for (int i = tid; i < NPIX; i += 256) s += p[i];
    __shared__ float sm[256];
    sm[tid] = s;
    __syncthreads();
    for (int off = 128; off; off >>= 1) {
        if (tid < off) sm[tid] += sm[tid + off];
        __syncthreads();
    }
    if (tid == 0) g_gmean[ch] = sm[0] * (1.0f / (float)NPIX);
}

// ---------------- 3) head(g) folded into bp1 ----------------
__global__ void head_const_kernel(const float* __restrict__ W1, const float* __restrict__ b1,
                                  const float* __restrict__ W2, const float* __restrict__ b2,
                                  const float* __restrict__ P1, const float* __restrict__ bp1) {
    __shared__ float gs[64];
    __shared__ float t[128];
    __shared__ float hg[64];
    int tid = threadIdx.x;  // 128 threads
    if (tid < 64) gs[tid] = g_gmean[tid];
    __syncthreads();
    float a = b1[tid];
    #pragma unroll 8
    for (int c = 0; c < 64; c++) a = fmaf(gs[c], W1[c * 128 + tid], a);
    t[tid] = fmaxf(a, 0.f);
    __syncthreads();
    if (tid < 64) {
        float a2 = b2[tid];
        #pragma unroll 8
        for (int k = 0; k < 128; k++) a2 = fmaf(t[k], W2[k * 64 + tid], a2);
        hg[tid] = fmaxf(a2, 0.f);
    }
    __syncthreads();
    float be = bp1[tid];
    #pragma unroll 8
    for (int c = 0; c < 64; c++) be = fmaf(hg[c], P1[(192 + c) * 128 + tid], be);
    g_bp1eff[tid] = be;
}

// ---------------- 4) pooling: 4 samples/warp-iter, 8 lanes x 8 channels each ----------------
template<int S>
__device__ __forceinline__ void pool_roi_v(int n, int lane,
                                           const float* __restrict__ boxes,
                                           float* __restrict__ outb) {
    constexpr int SS = S * S;
    int sub = lane >> 3;   // sample slot 0..3
    int cl  = lane & 7;    // channel group: half2 idx cl*4..cl*4+3 (8 channels)

    float bx1 = __ldg(&boxes[n * 4 + 0]);
    float by1 = __ldg(&boxes[n * 4 + 1]);
    float bx2 = __ldg(&boxes[n * 4 + 2]);
    float by2 = __ldg(&boxes[n * 4 + 3]);
    float nx1 = bx1 * (2.0f / 960.0f) - 1.0f;
    float ny1 = by1 * (2.0f / 960.0f) - 1.0f;
    float nx2 = bx2 * (2.0f / 960.0f) - 1.0f;
    float ny2 = by2 * (2.0f / 960.0f) - 1.0f;
    float cx = (nx1 + nx2) * 0.5f;
    float cy = (ny1 + ny2) * 0.5f;
    float w  = fmaxf(nx2 - nx1, 1e-6f);
    float h  = fmaxf(ny2 - ny1, 1e-6f);
    float stepx = w * (120.0f / (float)S);
    float stepy = h * (120.0f / (float)S);
    float ixb = fmaf(w * 60.0f, (1.0f / (float)S - 1.0f), fmaf(cx, 120.0f, 119.5f));
    float iyb = fmaf(h * 60.0f, (1.0f / (float)S - 1.0f), fmaf(cy, 120.0f, 119.5f));

    float acc[8];
    #pragma unroll
    for (int k = 0; k < 8; k++) acc[k] = 0.f;

    const uint4* fm4 = (const uint4*)g_fmTh;  // one uint4 = 4 half2 = 8 channels

    #pragma unroll 2
    for (int base = 0; base < SS; base += 4) {
        int samp = base + sub;
        bool alive = (samp < SS);
        int sc = alive ? samp : 0;
        int i = sc / S;          // const-divide -> mul/shift
        int j = sc - i * S;
        float ix = fmaf((float)j, stepx, ixb);
        float iy = fmaf((float)i, stepy, iyb);
        float x0f = floorf(ix), y0f = floorf(iy);
        float dx = ix - x0f, dy = iy - y0f;
        int x0 = (int)x0f, y0 = (int)y0f;
        int x1 = x0 + 1,   y1 = y0 + 1;
        float wx0 = ((unsigned)x0 < FW) ? (1.f - dx) : 0.f;
        float wx1 = ((unsigned)x1 < FW) ? dx : 0.f;
        float wy0 = (alive && (unsigned)y0 < FH) ? (1.f - dy) : 0.f;
        float wy1 = (alive && (unsigned)y1 < FH) ? dy : 0.f;
        int xc0 = max(0, min(x0, FW - 1));
        int xc1 = max(0, min(x1, FW - 1));
        int yc0 = max(0, min(y0, FH - 1));
        int yc1 = max(0, min(y1, FH - 1));
        int r0 = yc0 * FW, r1 = yc1 * FW;
        uint4 q00 = __ldg(&fm4[(r0 + xc0) * 8 + cl]);
        uint4 q01 = __ldg(&fm4[(r0 + xc1) * 8 + cl]);
        uint4 q10 = __ldg(&fm4[(r1 + xc0) * 8 + cl]);
        uint4 q11 = __ldg(&fm4[(r1 + xc1) * 8 + cl]);
        const unsigned* u00 = &q00.x;
        const unsigned* u01 = &q01.x;
        const unsigned* u10 = &q10.x;
        const unsigned* u11 = &q11.x;
        #pragma unroll
        for (int k = 0; k < 4; k++) {
            float2 f00 = __half22float2(*(const __half2*)&u00[k]);
            float2 f01 = __half22float2(*(const __half2*)&u01[k]);
            float2 f10 = __half22float2(*(const __half2*)&u10[k]);
            float2 f11 = __half22float2(*(const __half2*)&u11[k]);
            float tx = fmaf(f00.x, wx0, f01.x * wx1);
            float ty = fmaf(f00.y, wx0, f01.y * wx1);
            float bx = fmaf(f10.x, wx0, f11.x * wx1);
            float by = fmaf(f10.y, wx0, f11.y * wx1);
            acc[2 * k]     = fmaf(wy0, tx, fmaf(wy1, bx, acc[2 * k]));
            acc[2 * k + 1] = fmaf(wy0, ty, fmaf(wy1, by, acc[2 * k + 1]));
        }
    }

    // reduce across sample slots (sub 0..3): lanes l, l+8, l+16, l+24
    #pragma unroll
    for (int k = 0; k < 8; k++) {
        acc[k] += __shfl_down_sync(0xffffffffu, acc[k], 16);
        acc[k] += __shfl_down_sync(0xffffffffu, acc[k], 8);
    }
    if (sub == 0) {
        const float inv = 1.0f / (float)SS;
        float4* o = (float4*)&outb[(size_t)n * 64 + cl * 8];
        o[0] = make_float4(acc[0] * inv, acc[1] * inv, acc[2] * inv, acc[3] * inv);
        o[1] = make_float4(acc[4] * inv, acc[5] * inv, acc[6] * inv, acc[7] * inv);
    }
}

// LPT ordering: heavy S=11 tasks first, S=3 last (tail-filler).
__global__ void pool_all_kernel(const float* __restrict__ boxes) {
    int tid  = threadIdx.x;
    int lane = tid & 31;
    int warp = tid >> 5;
    int task = blockIdx.x * 8 + warp;     // 0..11999
    if (task < NROI) {
        pool_roi_v<11>(task, lane, boxes, g_pooled + (size_t)2 * NROI * CCH);
    } else if (task < 2 * NROI) {
        pool_roi_v<7>(task - NROI, lane, boxes, g_pooled + (size_t)NROI * CCH);
    } else {
        pool_roi_v<3>(task - 2 * NROI, lane, boxes, g_pooled);
    }
}

// ---------------- 5) per-scale MLP head: relu(relu(X@W1+b1)@W2+b2) ----------------
__global__ void head_kernel(const float* __restrict__ W1, const float* __restrict__ b1,
                            const float* __restrict__ W2, const float* __restrict__ b2) {
    extern __shared__ float sh[];
    float* As  = sh;                 // 64*64
    float* W1s = As + 4096;          // 64*128
    float* W2s = W1s + 8192;         // 128*64
    float* Ts  = W2s + 8192;         // 64*128
    float* b1s = Ts + 8192;          // 128
    float* b2s = b1s + 128;          // 64

    int tid = threadIdx.x;
    int scale = blockIdx.y;
    int row0 = blockIdx.x * 64;
    const float* X    = g_pooled + (size_t)scale * NROI * CCH;
    float*       Hout = g_h      + (size_t)scale * NROI * CCH;

    {
        const float4* X4 = (const float4*)(X + (size_t)row0 * 64);
        float4* As4 = (float4*)As;
        #pragma unroll
        for (int idx = tid; idx < 1024; idx += 256) {
            int r = idx >> 4;
            As4[idx] = (row0 + r < NROI) ? X4[idx] : make_float4(0.f, 0.f, 0.f, 0.f);
        }
        const float4* W14 = (const float4*)W1;
        float4* W1s4 = (float4*)W1s;
        #pragma unroll
        for (int idx = tid; idx < 2048; idx += 256) W1s4[idx] = W14[idx];
        const float4* W24 = (const float4*)W2;
        float4* W2s4 = (float4*)W2s;
        #pragma unroll
        for (int idx = tid; idx < 2048; idx += 256) W2s4[idx] = W24[idx];
        if (tid < 128) b1s[tid] = b1[tid];
        if (tid < 64)  b2s[tid] = b2[tid];
    }
    __syncthreads();

    int rg = tid >> 4;
    int cg = tid & 15;

    float acc[4][8];
    #pragma unroll
    for (int i = 0; i < 4; i++)
        #pragma unroll
        for (int j = 0; j < 8; j++) acc[i][j] = 0.f;

    #pragma unroll 4
    for (int k = 0; k < 64; k++) {
        float a[4];
        #pragma unroll
        for (int i = 0; i < 4; i++) a[i] = As[(rg * 4 + i) * 64 + k];
        float4 w0 = *(const float4*)&W1s[k * 128 + cg * 8];
        float4 w1 = *(const float4*)&W1s[k * 128 + cg * 8 + 4];
        float wv[8] = {w0.x, w0.y, w0.z, w0.w, w1.x, w1.y, w1.z, w1.w};
        #pragma unroll
        for (int i = 0; i < 4; i++)
            #pragma unroll
            for (int j = 0; j < 8; j++)
                acc[i][j] = fmaf(a[i], wv[j], acc[i][j]);
    }
    #pragma unroll
    for (int i = 0; i < 4; i++) {
        int r = rg * 4 + i;
        #pragma unroll
        for (int j = 0; j < 8; j++)
            Ts[r * 128 + cg * 8 + j] = fmaxf(acc[i][j] + b1s[cg * 8 + j], 0.f);
    }
    __syncthreads();

    int cg2 = tid & 15;
    float acc2[4][4];
    #pragma unroll
    for (int i = 0; i < 4; i++)
        #pragma unroll
        for (int j = 0; j < 4; j++) acc2[i][j] = 0.f;

    #pragma unroll 4
    for (int k = 0; k < 128; k++) {
        float a[4];
        #pragma unroll
        for (int i = 0; i < 4; i++) a[i] = Ts[(rg * 4 + i) * 128 + k];
        float4 w = *(const float4*)&W2s[k * 64 + cg2 * 4];
        float wv[4] = {w.x, w.y, w.z, w.w};
        #pragma unroll
        for (int i = 0; i < 4; i++)
            #pragma unroll
            for (int j = 0; j < 4; j++)
                acc2[i][j] = fmaf(a[i], wv[j], acc2[i][j]);
    }
    #pragma unroll
    for (int i = 0; i < 4; i++) {
        int r = row0 + rg * 4 + i;
        if (r < NROI) {
            float4 o;
            o.x = fmaxf(acc2[i][0] + b2s[cg2 * 4 + 0], 0.f);
            o.y = fmaxf(acc2[i][1] + b2s[cg2 * 4 + 1], 0.f);
            o.z = fmaxf(acc2[i][2] + b2s[cg2 * 4 + 2], 0.f);
            o.w = fmaxf(acc2[i][3] + b2s[cg2 * 4 + 3], 0.f);
            *(float4*)&Hout[(size_t)r * 64 + cg2 * 4] = o;
        }
    }
}

// ---------------- 6) final: 32-row tiles, out = relu(relu(cat@P1+bp1eff)@P2+bp2) ----------------
__global__ void final_kernel(const float* __restrict__ P1, const float* __restrict__ P2,
                             const float* __restrict__ bp2, float* __restrict__ out) {
    extern __shared__ float sh[];
    float* As  = sh;                 // 32*64 (per chunk)
    float* P1s = As + 2048;          // 64*128 (per chunk)
    float* P2s = P1s + 8192;         // 128*64
    float* Ts  = P2s + 8192;         // 32*128
    float* be  = Ts + 4096;          // 128
    float* b2s = be + 128;           // 64

    int tid = threadIdx.x;
    int row0 = blockIdx.x * 32;

    {
        const float4* P24 = (const float4*)P2;
        float4* P2s4 = (float4*)P2s;
        #pragma unroll
        for (int idx = tid; idx < 2048; idx += 256) P2s4[idx] = P24[idx];
        if (tid < 128) be[tid] = g_bp1eff[tid];
        if (tid < 64)  b2s[tid] = bp2[tid];
    }

    int rg = tid >> 4;   // 0..15 -> rows rg*2, rg*2+1
    int cg = tid & 15;   // cols cg*8..+7

    float acc[2][8];
    #pragma unroll
    for (int i = 0; i < 2; i++)
        #pragma unroll
        for (int j = 0; j < 8; j++) acc[i][j] = 0.f;

    for (int kb = 0; kb < 3; kb++) {
        __syncthreads();
        const float4* X4 = (const float4*)(g_h + (size_t)kb * NROI * CCH + (size_t)row0 * 64);
        float4* As4 = (float4*)As;
        #pragma unroll
        for (int idx = tid; idx < 512; idx += 256) {
            int r = idx >> 4;
            As4[idx] = (row0 + r < NROI) ? X4[idx] : make_float4(0.f, 0.f, 0.f, 0.f);
        }
        const float4* P14 = (const float4*)(P1 + (size_t)kb * 64 * 128);
        float4* P1s4 = (float4*)P1s;
        #pragma unroll
        for (int idx = tid; idx < 2048; idx += 256) P1s4[idx] = P14[idx];
        __syncthreads();

        #pragma unroll 4
        for (int k = 0; k < 64; k++) {
            float a[2];
            #pragma unroll
            for (int i = 0; i < 2; i++) a[i] = As[(rg * 2 + i) * 64 + k];
            float4 w0 = *(const float4*)&P1s[k * 128 + cg * 8];
            float4 w1 = *(const float4*)&P1s[k * 128 + cg * 8 + 4];
            float wv[8] = {w0.x, w0.y, w0.z, w0.w, w1.x, w1.y, w1.z, w1.w};
            #pragma unroll
            for (int i = 0; i < 2; i++)
                #pragma unroll
                for (int j = 0; j < 8; j++)
                    acc[i][j] = fmaf(a[i], wv[j], acc[i][j]);
        }
    }

    #pragma unroll
    for (int i = 0; i < 2; i++) {
        int r = rg * 2 + i;
        #pragma unroll
        for (int j = 0; j < 8; j++)
            Ts[r * 128 + cg * 8 + j] = fmaxf(acc[i][j] + be[cg * 8 + j], 0.f);
    }
    __syncthreads();

    int cg2 = tid & 15;
    float acc2[2][4];
    #pragma unroll
    for (int i = 0; i < 2; i++)
        #pragma unroll
        for (int j = 0; j < 4; j++) acc2[i][j] = 0.f;

    #pragma unroll 4
    for (int k = 0; k < 128; k++) {
        float a[2];
        #pragma unroll
        for (int i = 0; i < 2; i++) a[i] = Ts[(rg * 2 + i) * 128 + k];
        float4 w = *(const float4*)&P2s[k * 64 + cg2 * 4];
        float wv[4] = {w.x, w.y, w.z, w.w};
        #pragma unroll
        for (int i = 0; i < 2; i++)
            #pragma unroll
            for (int j = 0; j < 4; j++)
                acc2[i][j] = fmaf(a[i], wv[j], acc2[i][j]);
    }
    #pragma unroll
    for (int i = 0; i < 2; i++) {
        int r = row0 + rg * 2 + i;
        if (r < NROI) {
            float4 o;
            o.x = fmaxf(acc2[i][0] + b2s[cg2 * 4 + 0], 0.f);
            o.y = fmaxf(acc2[i][1] + b2s[cg2 * 4 + 1], 0.f);
            o.z = fmaxf(acc2[i][2] + b2s[cg2 * 4 + 2], 0.f);
            o.w = fmaxf(acc2[i][3] + b2s[cg2 * 4 + 3], 0.f);
            *(float4*)&out[(size_t)r * 64 + cg2 * 4] = o;
        }
    }
}

// ---------------- launch ----------------
extern "C" void kernel_launch(void* const* d_in, const int* in_sizes, int n_in,
                              void* d_out, int out_size) {
    const float* fm    = (const float*)d_in[0];
    const float* boxes = (const float*)d_in[1];
    const float* W1    = (const float*)d_in[2];
    const float* b1    = (const float*)d_in[3];
    const float* W2    = (const float*)d_in[4];
    const float* b2    = (const float*)d_in[5];
    const float* P1    = (const float*)d_in[6];
    const float* bp1   = (const float*)d_in[7];
    const float* P2    = (const float*)d_in[8];
    const float* bp2   = (const float*)d_in[9];
    float* out = (float*)d_out;

    const int SMEM_H = (4096 + 8192 + 8192 + 8192 + 128 + 64) * 4;
    const int SMEM_F = (2048 + 8192 + 8192 + 4096 + 128 + 64) * 4;
    cudaFuncSetAttribute(head_kernel,  cudaFuncAttributeMaxDynamicSharedMemorySize, SMEM_H);
    cudaFuncSetAttribute(final_kernel, cudaFuncAttributeMaxDynamicSharedMemorySize, SMEM_F);

    transpose_kernel<<<NPIX / 64, 256>>>(fm);
    gmean_kernel<<<64, 256>>>(fm);
    head_const_kernel<<<1, 128>>>(W1, b1, W2, b2, P1, bp1);

    const int PB = (3 * NROI) / 8;  // 1500 blocks, 8 warps each (exact)
    pool_all_kernel<<<PB, 256>>>(boxes);

    const int NT = (NROI + 63) / 64;    // 63 row tiles
    dim3 hgrid(NT, 3);
    head_kernel<<<hgrid, 256, SMEM_H>>>(W1, b1, W2, b2);

    const int NT2 = (NROI + 31) / 32;   // 125 row tiles
    final_kernel<<<NT2, 256, SMEM_F>>>(P1, P2, bp2, out);
}

// round 6
// speedup vs baseline: 2.7527x; 1.0979x over previous
#include <cuda_runtime.h>
#include <cuda_fp16.h>

#define NROI 4000
#define CCH  64
#define FH   240
#define FW   240
#define NPIX (FH*FW)

// ---------------- scratch (no allocations allowed) ----------------
__device__ __align__(16) __half2 g_fmTh[NPIX * 32]; // HWC fp16 fm (7.4 MB), 32 half2 = 64ch
__device__ float g_pooled[3 * NROI * CCH]; // pooled features per scale
__device__ float g_h[3 * NROI * CCH];      // head outputs per scale
__device__ float g_gmean[CCH];             // global mean per channel
__device__ float g_bp1eff[128];            // bp1 + head(g) @ P1[192:256]

// ---------------- 1) transpose CHW fp32 -> HWC fp16 (half2 packed) ----------------
__global__ void transpose_kernel(const float* __restrict__ fm) {
    __shared__ float tile[64][65];
    int pix0 = blockIdx.x * 64;
    int tid  = threadIdx.x;
    int lane = tid & 63;     // pixel offset on load
    int grp  = tid >> 6;     // 0..3
    #pragma unroll
    for (int c = grp; c < 64; c += 4)
        tile[c][lane] = fm[c * NPIX + pix0 + lane];
    __syncthreads();
    int c2 = tid & 31;       // channel pair
    int pg = tid >> 5;       // 0..7
    #pragma unroll
    for (int p = pg; p < 64; p += 8)
        g_fmTh[(pix0 + p) * 32 + c2] =
            __floats2half2_rn(tile[2 * c2][p], tile[2 * c2 + 1][p]);
}

// ---------------- 2) global channel mean (fp32 source) ----------------
__global__ void gmean_kernel(const float* __restrict__ fm) {
    int ch = blockIdx.x, tid = threadIdx.x;
    const float* p = fm + ch * NPIX;
    float s = 0.f;
    for (int i = tid; i < NPIX; i += 256) s += p[i];
    __shared__ float sm[256];
    sm[tid] = s;
    __syncthreads();
    for (int off = 128; off; off >>= 1) {
        if (tid < off) sm[tid] += sm[tid + off];
        __syncthreads();
    }
    if (tid == 0) g_gmean[ch] = sm[0] * (1.0f / (float)NPIX);
}

// ---------------- 3) head(g) folded into bp1 ----------------
__global__ void head_const_kernel(const float* __restrict__ W1, const float* __restrict__ b1,
                                  const float* __restrict__ W2, const float* __restrict__ b2,
                                  const float* __restrict__ P1, const float* __restrict__ bp1) {
    __shared__ float gs[64];
    __shared__ float t[128];
    __shared__ float hg[64];
    int tid = threadIdx.x;  // 128 threads
    if (tid < 64) gs[tid] = g_gmean[tid];
    __syncthreads();
    float a = b1[tid];
    #pragma unroll 8
    for (int c = 0; c < 64; c++) a = fmaf(gs[c], W1[c * 128 + tid], a);
    t[tid] = fmaxf(a, 0.f);
    __syncthreads();
    if (tid < 64) {
        float a2 = b2[tid];
        #pragma unroll 8
        for (int k = 0; k < 128; k++) a2 = fmaf(t[k], W2[k * 64 + tid], a2);
        hg[tid] = fmaxf(a2, 0.f);
    }
    __syncthreads();
    float be = bp1[tid];
    #pragma unroll 8
    for (int c = 0; c < 64; c++) be = fmaf(hg[c], P1[(192 + c) * 128 + tid], be);
    g_bp1eff[tid] = be;
}

// ---------------- 4) pooling: 4 samples/warp-iter, HFMA2 bilinear ----------------
template<int S>
__device__ __forceinline__ void pool_roi_v(int n, int lane,
                                           const float* __restrict__ boxes,
                                           float* __restrict__ outb) {
    constexpr int SS = S * S;
    int sub = lane >> 3;   // sample slot 0..3
    int cl  = lane & 7;    // channel group: half2 idx cl*4..cl*4+3 (8 channels)

    float bx1 = __ldg(&boxes[n * 4 + 0]);
    float by1 = __ldg(&boxes[n * 4 + 1]);
    float bx2 = __ldg(&boxes[n * 4 + 2]);
    float by2 = __ldg(&boxes[n * 4 + 3]);
    float nx1 = bx1 * (2.0f / 960.0f) - 1.0f;
    float ny1 = by1 * (2.0f / 960.0f) - 1.0f;
    float nx2 = bx2 * (2.0f / 960.0f) - 1.0f;
    float ny2 = by2 * (2.0f / 960.0f) - 1.0f;
    float cx = (nx1 + nx2) * 0.5f;
    float cy = (ny1 + ny2) * 0.5f;
    float w  = fmaxf(nx2 - nx1, 1e-6f);
    float h  = fmaxf(ny2 - ny1, 1e-6f);
    float stepx = w * (120.0f / (float)S);
    float stepy = h * (120.0f / (float)S);
    float ixb = fmaf(w * 60.0f, (1.0f / (float)S - 1.0f), fmaf(cx, 120.0f, 119.5f));
    float iyb = fmaf(h * 60.0f, (1.0f / (float)S - 1.0f), fmaf(cy, 120.0f, 119.5f));

    float acc[8];
    #pragma unroll
    for (int k = 0; k < 8; k++) acc[k] = 0.f;

    const uint4* fm4 = (const uint4*)g_fmTh;  // one uint4 = 4 half2 = 8 channels

    #pragma unroll 2
    for (int base = 0; base < SS; base += 4) {
        int samp = base + sub;
        bool alive = (samp < SS);
        int sc = alive ? samp : 0;
        int i = sc / S;          // const-divide -> mul/shift
        int j = sc - i * S;
        float ix = fmaf((float)j, stepx, ixb);
        float iy = fmaf((float)i, stepy, iyb);
        float x0f = floorf(ix), y0f = floorf(iy);
        float dx = ix - x0f, dy = iy - y0f;
        int x0 = (int)x0f, y0 = (int)y0f;
        int x1 = x0 + 1,   y1 = y0 + 1;
        float wx0 = ((unsigned)x0 < FW) ? (1.f - dx) : 0.f;
        float wx1 = ((unsigned)x1 < FW) ? dx : 0.f;
        float wy0 = (alive && (unsigned)y0 < FH) ? (1.f - dy) : 0.f;
        float wy1 = (alive && (unsigned)y1 < FH) ? dy : 0.f;
        int xc0 = max(0, min(x0, FW - 1));
        int xc1 = max(0, min(x1, FW - 1));
        int yc0 = max(0, min(y0, FH - 1));
        int yc1 = max(0, min(y1, FH - 1));
        int r0 = yc0 * FW, r1 = yc1 * FW;
        uint4 q00 = __ldg(&fm4[(r0 + xc0) * 8 + cl]);
        uint4 q01 = __ldg(&fm4[(r0 + xc1) * 8 + cl]);
        uint4 q10 = __ldg(&fm4[(r1 + xc0) * 8 + cl]);
        uint4 q11 = __ldg(&fm4[(r1 + xc1) * 8 + cl]);
        // corner weights in half2 (broadcast)
        __half2 h00 = __float2half2_rn(wy0 * wx0);
        __half2 h01 = __float2half2_rn(wy0 * wx1);
        __half2 h10 = __float2half2_rn(wy1 * wx0);
        __half2 h11 = __float2half2_rn(wy1 * wx1);
        const __half2* f00 = (const __half2*)&q00;
        const __half2* f01 = (const __half2*)&q01;
        const __half2* f10 = (const __half2*)&q10;
        const __half2* f11 = (const __half2*)&q11;
        #pragma unroll
        for (int k = 0; k < 4; k++) {
            __half2 s = __hmul2(h00, f00[k]);
            s = __hfma2(h01, f01[k], s);
            s = __hfma2(h10, f10[k], s);
            s = __hfma2(h11, f11[k], s);
            float2 fs = __half22float2(s);
            acc[2 * k]     += fs.x;
            acc[2 * k + 1] += fs.y;
        }
    }

    // reduce across sample slots (sub 0..3): lanes l, l+8, l+16, l+24
    #pragma unroll
    for (int k = 0; k < 8; k++) {
        acc[k] += __shfl_down_sync(0xffffffffu, acc[k], 16);
        acc[k] += __shfl_down_sync(0xffffffffu, acc[k], 8);
    }
    if (sub == 0) {
        const float inv = 1.0f / (float)SS;
        float4* o = (float4*)&outb[(size_t)n * 64 + cl * 8];
        o[0] = make_float4(acc[0] * inv, acc[1] * inv, acc[2] * inv, acc[3] * inv);
        o[1] = make_float4(acc[4] * inv, acc[5] * inv, acc[6] * inv, acc[7] * inv);
    }
}

// LPT ordering: heavy S=11 tasks first, S=3 last (tail-filler).
__global__ void pool_all_kernel(const float* __restrict__ boxes) {
    int tid  = threadIdx.x;
    int lane = tid & 31;
    int warp = tid >> 5;
    int task = blockIdx.x * 8 + warp;     // 0..11999
    if (task < NROI) {
        pool_roi_v<11>(task, lane, boxes, g_pooled + (size_t)2 * NROI * CCH);
    } else if (task < 2 * NROI) {
        pool_roi_v<7>(task - NROI, lane, boxes, g_pooled + (size_t)NROI * CCH);
    } else {
        pool_roi_v<3>(task - 2 * NROI, lane, boxes, g_pooled);
    }
}

// ---------------- 5) per-scale MLP head: relu(relu(X@W1+b1)@W2+b2) ----------------
__global__ void head_kernel(const float* __restrict__ W1, const float* __restrict__ b1,
                            const float* __restrict__ W2, const float* __restrict__ b2) {
    extern __shared__ float sh[];
    float* As  = sh;                 // 64*64
    float* W1s = As + 4096;          // 64*128
    float* W2s = W1s + 8192;         // 128*64
    float* Ts  = W2s + 8192;         // 64*128
    float* b1s = Ts + 8192;          // 128
    float* b2s = b1s + 128;          // 64

    int tid = threadIdx.x;
    int scale = blockIdx.y;
    int row0 = blockIdx.x * 64;
    const float* X    = g_pooled + (size_t)scale * NROI * CCH;
    float*       Hout = g_h      + (size_t)scale * NROI * CCH;

    {
        const float4* X4 = (const float4*)(X + (size_t)row0 * 64);
        float4* As4 = (float4*)As;
        #pragma unroll
        for (int idx = tid; idx < 1024; idx += 256) {
            int r = idx >> 4;
            As4[idx] = (row0 + r < NROI) ? X4[idx] : make_float4(0.f, 0.f, 0.f, 0.f);
        }
        const float4* W14 = (const float4*)W1;
        float4* W1s4 = (float4*)W1s;
        #pragma unroll
        for (int idx = tid; idx < 2048; idx += 256) W1s4[idx] = W14[idx];
        const float4* W24 = (const float4*)W2;
        float4* W2s4 = (float4*)W2s;
        #pragma unroll
        for (int idx = tid; idx < 2048; idx += 256) W2s4[idx] = W24[idx];
        if (tid < 128) b1s[tid] = b1[tid];
        if (tid < 64)  b2s[tid] = b2[tid];
    }
    __syncthreads();

    int rg = tid >> 4;
    int cg = tid & 15;

    // phase A: T = relu(A@W1 + b1), 64x128, float4-over-k shared loads
    float acc[4][8];
    #pragma unroll
    for (int i = 0; i < 4; i++)
        #pragma unroll
        for (int j = 0; j < 8; j++) acc[i][j] = 0.f;

    #pragma unroll 4
    for (int k0 = 0; k0 < 64; k0 += 4) {
        float4 a4[4];
        #pragma unroll
        for (int i = 0; i < 4; i++)
            a4[i] = *(const float4*)&As[(rg * 4 + i) * 64 + k0];
        #pragma unroll
        for (int kk = 0; kk < 4; kk++) {
            float4 w0 = *(const float4*)&W1s[(k0 + kk) * 128 + cg * 8];
            float4 w1 = *(const float4*)&W1s[(k0 + kk) * 128 + cg * 8 + 4];
            float wv[8] = {w0.x, w0.y, w0.z, w0.w, w1.x, w1.y, w1.z, w1.w};
            #pragma unroll
            for (int i = 0; i < 4; i++) {
                float av = (&a4[i].x)[kk];
                #pragma unroll
                for (int j = 0; j < 8; j++)
                    acc[i][j] = fmaf(av, wv[j], acc[i][j]);
            }
        }
    }
    #pragma unroll
    for (int i = 0; i < 4; i++) {
        int r = rg * 4 + i;
        #pragma unroll
        for (int j = 0; j < 8; j++)
            Ts[r * 128 + cg * 8 + j] = fmaxf(acc[i][j] + b1s[cg * 8 + j], 0.f);
    }
    __syncthreads();

    // phase B: H = relu(T@W2 + b2), 64x64
    int cg2 = tid & 15;
    float acc2[4][4];
    #pragma unroll
    for (int i = 0; i < 4; i++)
        #pragma unroll
        for (int j = 0; j < 4; j++) acc2[i][j] = 0.f;

    #pragma unroll 4
    for (int k0 = 0; k0 < 128; k0 += 4) {
        float4 a4[4];
        #pragma unroll
        for (int i = 0; i < 4; i++)
            a4[i] = *(const float4*)&Ts[(rg * 4 + i) * 128 + k0];
        #pragma unroll
        for (int kk = 0; kk < 4; kk++) {
            float4 wq = *(const float4*)&W2s[(k0 + kk) * 64 + cg2 * 4];
            float wv[4] = {wq.x, wq.y, wq.z, wq.w};
            #pragma unroll
            for (int i = 0; i < 4; i++) {
                float av = (&a4[i].x)[kk];
                #pragma unroll
                for (int j = 0; j < 4; j++)
                    acc2[i][j] = fmaf(av, wv[j], acc2[i][j]);
            }
        }
    }
    #pragma unroll
    for (int i = 0; i < 4; i++) {
        int r = row0 + rg * 4 + i;
        if (r < NROI) {
            float4 o;
            o.x = fmaxf(acc2[i][0] + b2s[cg2 * 4 + 0], 0.f);
            o.y = fmaxf(acc2[i][1] + b2s[cg2 * 4 + 1], 0.f);
            o.z = fmaxf(acc2[i][2] + b2s[cg2 * 4 + 2], 0.f);
            o.w = fmaxf(acc2[i][3] + b2s[cg2 * 4 + 3], 0.f);
            *(float4*)&Hout[(size_t)r * 64 + cg2 * 4] = o;
        }
    }
}

// ---------------- 6) final: 32-row tiles, out = relu(relu(cat@P1+bp1eff)@P2+bp2) ----------------
__global__ void final_kernel(const float* __restrict__ P1, const float* __restrict__ P2,
                             const float* __restrict__ bp2, float* __restrict__ out) {
    extern __shared__ float sh[];
    float* As  = sh;                 // 32*64 (per chunk)
    float* P1s = As + 2048;          // 64*128 (per chunk)
    float* P2s = P1s + 8192;         // 128*64
    float* Ts  = P2s + 8192;         // 32*128
    float* be  = Ts + 4096;          // 128
    float* b2s = be + 128;           // 64

    int tid = threadIdx.x;
    int row0 = blockIdx.x * 32;

    {
        const float4* P24 = (const float4*)P2;
        float4* P2s4 = (float4*)P2s;
        #pragma unroll
        for (int idx = tid; idx < 2048; idx += 256) P2s4[idx] = P24[idx];
        if (tid < 128) be[tid] = g_bp1eff[tid];
        if (tid < 64)  b2s[tid] = bp2[tid];
    }

    int rg = tid >> 4;   // 0..15 -> rows rg*2, rg*2+1
    int cg = tid & 15;   // cols cg*8..+7

    float acc[2][8];
    #pragma unroll
    for (int i = 0; i < 2; i++)
        #pragma unroll
        for (int j = 0; j < 8; j++) acc[i][j] = 0.f;

    for (int kb = 0; kb < 3; kb++) {
        __syncthreads();
        const float4* X4 = (const float4*)(g_h + (size_t)kb * NROI * CCH + (size_t)row0 * 64);
        float4* As4 = (float4*)As;
        #pragma unroll
        for (int idx = tid; idx < 512; idx += 256) {
            int r = idx >> 4;
            As4[idx] = (row0 + r < NROI) ? X4[idx] : make_float4(0.f, 0.f, 0.f, 0.f);
        }
        const float4* P14 = (const float4*)(P1 + (size_t)kb * 64 * 128);
        float4* P1s4 = (float4*)P1s;
        #pragma unroll
        for (int idx = tid; idx < 2048; idx += 256) P1s4[idx] = P14[idx];
        __syncthreads();

        #pragma unroll 4
        for (int k0 = 0; k0 < 64; k0 += 4) {
            float4 a4[2];
            #pragma unroll
            for (int i = 0; i < 2; i++)
                a4[i] = *(const float4*)&As[(rg * 2 + i) * 64 + k0];
            #pragma unroll
            for (int kk = 0; kk < 4; kk++) {
                float4 w0 = *(const float4*)&P1s[(k0 + kk) * 128 + cg * 8];
                float4 w1 = *(const float4*)&P1s[(k0 + kk) * 128 + cg * 8 + 4];
                float wv[8] = {w0.x, w0.y, w0.z, w0.w, w1.x, w1.y, w1.z, w1.w};
                #pragma unroll
                for (int i = 0; i < 2; i++) {
                    float av = (&a4[i].x)[kk];
                    #pragma unroll
                    for (int j = 0; j < 8; j++)
                        acc[i][j] = fmaf(av, wv[j], acc[i][j]);
                }
            }
        }
    }

    #pragma unroll
    for (int i = 0; i < 2; i++) {
        int r = rg * 2 + i;
        #pragma unroll
        for (int j = 0; j < 8; j++)
            Ts[r * 128 + cg * 8 + j] = fmaxf(acc[i][j] + be[cg * 8 + j], 0.f);
    }
    __syncthreads();

    int cg2 = tid & 15;
    float acc2[2][4];
    #pragma unroll
    for (int i = 0; i < 2; i++)
        #pragma unroll
        for (int j = 0; j < 4; j++) acc2[i][j] = 0.f;

    #pragma unroll 4
    for (int k0 = 0; k0 < 128; k0 += 4) {
        float4 a4[2];
        #pragma unroll
        for (int i = 0; i < 2; i++)
            a4[i] = *(const float4*)&Ts[(rg * 2 + i) * 128 + k0];
        #pragma unroll
        for (int kk = 0; kk < 4; kk++) {
            float4 wq = *(const float4*)&P2s[(k0 + kk) * 64 + cg2 * 4];
            float wv[4] = {wq.x, wq.y, wq.z, wq.w};
            #pragma unroll
            for (int i = 0; i < 2; i++) {
                float av = (&a4[i].x)[kk];
                #pragma unroll
                for (int j = 0; j < 4; j++)
                    acc2[i][j] = fmaf(av, wv[j], acc2[i][j]);
            }
        }
    }
    #pragma unroll
    for (int i = 0; i < 2; i++) {
        int r = row0 + rg * 2 + i;
        if (r < NROI) {
            float4 o;
            o.x = fmaxf(acc2[i][0] + b2s[cg2 * 4 + 0], 0.f);
            o.y = fmaxf(acc2[i][1] + b2s[cg2 * 4 + 1], 0.f);
            o.z = fmaxf(acc2[i][2] + b2s[cg2 * 4 + 2], 0.f);
            o.w = fmaxf(acc2[i][3] + b2s[cg2 * 4 + 3], 0.f);
            *(float4*)&out[(size_t)r * 64 + cg2 * 4] = o;
        }
    }
}

// ---------------- launch ----------------
extern "C" void kernel_launch(void* const* d_in, const int* in_sizes, int n_in,
                              void* d_out, int out_size) {
    const float* fm    = (const float*)d_in[0];
    const float* boxes = (const float*)d_in[1];
    const float* W1    = (const float*)d_in[2];
    const float* b1    = (const float*)d_in[3];
    const float* W2    = (const float*)d_in[4];
    const float* b2    = (const float*)d_in[5];
    const float* P1    = (const float*)d_in[6];
    const float* bp1   = (const float*)d_in[7];
    const float* P2    = (const float*)d_in[8];
    const float* bp2   = (const float*)d_in[9];
    float* out = (float*)d_out;

    const int SMEM_H = (4096 + 8192 + 8192 + 8192 + 128 + 64) * 4;
    const int SMEM_F = (2048 + 8192 + 8192 + 4096 + 128 + 64) * 4;
    cudaFuncSetAttribute(head_kernel,  cudaFuncAttributeMaxDynamicSharedMemorySize, SMEM_H);
    cudaFuncSetAttribute(final_kernel, cudaFuncAttributeMaxDynamicSharedMemorySize, SMEM_F);

    transpose_kernel<<<NPIX / 64, 256>>>(fm);
    gmean_kernel<<<64, 256>>>(fm);
    head_const_kernel<<<1, 128>>>(W1, b1, W2, b2, P1, bp1);

    const int PB = (3 * NROI) / 8;  // 1500 blocks, 8 warps each (exact)
    pool_all_kernel<<<PB, 256>>>(boxes);

    const int NT = (NROI + 63) / 64;    // 63 row tiles
    dim3 hgrid(NT, 3);
    head_kernel<<<hgrid, 256, SMEM_H>>>(W1, b1, W2, b2);

    const int NT2 = (NROI + 31) / 32;   // 125 row tiles
    final_kernel<<<NT2, 256, SMEM_F>>>(P1, P2, bp2, out);
}